// round 8
// baseline (speedup 1.0000x reference)
#include <cuda_runtime.h>
#include <cuda_bf16.h>
#include <cstdint>

#define BB 32768
#define NI 256
#define NH 1024
#define NF 256

// ---------------- scratch (device globals; no allocs allowed) ----------------
__device__ __align__(16) __nv_bfloat16 g_a_hi[(size_t)BB * NI];
__device__ __align__(16) __nv_bfloat16 g_a_lo[(size_t)BB * NI];
__device__ __align__(16) __nv_bfloat16 g_w1_hi[NH * NI];
__device__ __align__(16) __nv_bfloat16 g_w1_lo[NH * NI];
__device__ __align__(16) __nv_bfloat16 g_w2_hi[NF * NH];
__device__ __align__(16) __nv_bfloat16 g_w2_lo[NF * NH];
__device__ __align__(16) __nv_bfloat16 g_h_hi[(size_t)BB * NH];
__device__ __align__(16) __nv_bfloat16 g_h_lo[(size_t)BB * NH];
__device__ __align__(16) float g_p[(size_t)BB * NF];

__device__ __forceinline__ uint32_t smem_u32(const void* p) {
    uint32_t a;
    asm("{ .reg .u64 t; cvta.to.shared.u64 t, %1; cvt.u32.u64 %0, t; }" : "=r"(a) : "l"(p));
    return a;
}
__device__ __forceinline__ void cp16(uint32_t saddr, const void* gaddr) {
    asm volatile("cp.async.cg.shared.global [%0], [%1], 16;\n" :: "r"(saddr), "l"(gaddr));
}
__device__ __forceinline__ void cp_commit() {
    asm volatile("cp.async.commit_group;\n" ::: "memory");
}
template <int N>
__device__ __forceinline__ void cp_wait() {
    asm volatile("cp.async.wait_group %0;\n" :: "n"(N) : "memory");
}
__device__ __forceinline__ void ldmx4(uint32_t* r, uint32_t addr) {
    asm volatile("ldmatrix.sync.aligned.m8n8.x4.shared.b16 {%0,%1,%2,%3}, [%4];"
                 : "=r"(r[0]), "=r"(r[1]), "=r"(r[2]), "=r"(r[3]) : "r"(addr));
}
__device__ __forceinline__ void mma16816(float* d, const uint32_t* a, uint32_t b0, uint32_t b1) {
    asm volatile(
        "mma.sync.aligned.m16n8k16.row.col.f32.bf16.bf16.f32 "
        "{%0,%1,%2,%3}, {%4,%5,%6,%7}, {%8,%9}, {%0,%1,%2,%3};"
        : "+f"(d[0]), "+f"(d[1]), "+f"(d[2]), "+f"(d[3])
        : "r"(a[0]), "r"(a[1]), "r"(a[2]), "r"(a[3]), "r"(b0), "r"(b1));
}

// ---------------- hi/lo split kernels ----------------
__global__ __launch_bounds__(256) void split_x(const float* __restrict__ x,
                                               __nv_bfloat16* __restrict__ hi,
                                               __nv_bfloat16* __restrict__ lo) {
    int i = blockIdx.x * 256 + threadIdx.x;           // i < BB*NI
    int r = i >> 8, c = i & 255;
    float v = x[(size_t)r * 257 + c];
    __nv_bfloat16 h = __float2bfloat16(v);
    hi[i] = h;
    lo[i] = __float2bfloat16(v - __bfloat162float(h));
}
__global__ __launch_bounds__(256) void split_w(const float* __restrict__ w,
                                               __nv_bfloat16* __restrict__ hi,
                                               __nv_bfloat16* __restrict__ lo, int n) {
    int i = blockIdx.x * 256 + threadIdx.x;
    if (i < n) {
        float v = w[i];
        __nv_bfloat16 h = __float2bfloat16(v);
        hi[i] = h;
        lo[i] = __float2bfloat16(v - __bfloat162float(h));
    }
}

// ---------------- HMMA GEMM (mma.sync m16n8k16 bf16, 3-pass hi/lo) ----------
// C[M,N] = A[M,K] @ B[N,K]^T + bias.  CTA tile 256x128x32, 16 warps (4x4),
// warp tile 64x32.  2-stage cp.async double buffer, 1 sync/iter, 1 CTA/SM.
// 3072 LDGSTS per iter for 2x the MMA work of the old 128x128 tile (1.67x
// fewer LSU ops per FLOP - the measured bottleneck).
// MODE 0: fp32 out.  MODE 1: relu + bf16 hi/lo out.
constexpr int PITCH  = 80;                  // 64B data + 16B pad per row
constexpr int A_TILE = 256 * PITCH;         // 20480 B per A tensor
constexpr int B_TILE = 128 * PITCH;         // 10240 B per B tensor
constexpr int B_OFF  = 2 * A_TILE;          // 40960
constexpr int STAGE  = 2 * A_TILE + 2 * B_TILE;   // 61440 B
constexpr int SMEM_BYTES = 2 * STAGE;       // 122880 B -> 1 CTA/SM

template <int MODE>
__global__ __launch_bounds__(512, 1) void hmma_gemm(
    const __nv_bfloat16* __restrict__ Ah, const __nv_bfloat16* __restrict__ Al,
    const __nv_bfloat16* __restrict__ Bh, const __nv_bfloat16* __restrict__ Bl,
    const float* __restrict__ bias, int K, int ldc,
    float* __restrict__ Cf,
    __nv_bfloat16* __restrict__ Chi, __nv_bfloat16* __restrict__ Clo)
{
    extern __shared__ __align__(128) char smem[];
    const uint32_t sb = smem_u32(smem);
    const int tid = threadIdx.x;
    const int w = tid >> 5, lane = tid & 31;
    const int wm = w >> 2, wn = w & 3;        // 4x4 warp grid, 64x32 warp tiles
    const int gid = lane >> 2, tig = lane & 3;
    const int m0 = blockIdx.y * 256, n0 = blockIdx.x * 128;

    float acc[4][4][4];
#pragma unroll
    for (int i = 0; i < 4; i++)
#pragma unroll
        for (int j = 0; j < 4; j++)
#pragma unroll
            for (int t = 0; t < 4; t++) acc[i][j][t] = 0.f;

    auto load_stage = [&](int s, int c) {
        const uint32_t st = sb + s * STAGE;
        const int k0 = c * 32;
        // A tiles: 256 rows x 4 chunks = 1024 cp16 per tensor
#pragma unroll
        for (int t = 0; t < 2; t++) {
            int idx = tid + t * 512;
            int row = idx >> 2, ch = idx & 3;
            uint32_t so = st + row * PITCH + ch * 16;
            size_t g = (size_t)(m0 + row) * K + k0 + ch * 8;
            cp16(so,          Ah + g);
            cp16(so + A_TILE, Al + g);
        }
        // B tiles: 128 rows x 4 chunks = 512 cp16 per tensor
        {
            int row = tid >> 2, ch = tid & 3;
            uint32_t so = st + B_OFF + row * PITCH + ch * 16;
            size_t g = (size_t)(n0 + row) * K + k0 + ch * 8;
            cp16(so,          Bh + g);
            cp16(so + B_TILE, Bl + g);
        }
    };

    auto compute_stage = [&](int s) {
        const uint32_t st = sb + s * STAGE;
        const uint32_t lsel = (lane & 15), hsel = (lane >> 4);
#pragma unroll
        for (int ks = 0; ks < 2; ks++) {
            uint32_t a_off = st + (wm * 64 + lsel) * PITCH + ks * 32 + hsel * 16;
            uint32_t b_off = st + B_OFF + (wn * 32 + lsel) * PITCH + ks * 32 + hsel * 16;
            uint32_t bh[2][4], bl[2][4];
#pragma unroll
            for (int p = 0; p < 2; p++) ldmx4(bh[p], b_off + p * 16 * PITCH);
#pragma unroll
            for (int p = 0; p < 2; p++) ldmx4(bl[p], b_off + p * 16 * PITCH + B_TILE);
#pragma unroll
            for (int i = 0; i < 4; i++) {
                uint32_t ah[4], al[4];
                ldmx4(ah, a_off + i * 16 * PITCH);
                ldmx4(al, a_off + i * 16 * PITCH + A_TILE);
#pragma unroll
                for (int j = 0; j < 4; j++) {
                    const int p = j >> 1, r = j & 1;
                    mma16816(acc[i][j], ah, bh[p][r], bh[p][r + 2]);
                }
#pragma unroll
                for (int j = 0; j < 4; j++) {
                    const int p = j >> 1, r = j & 1;
                    mma16816(acc[i][j], ah, bl[p][r], bl[p][r + 2]);
                }
#pragma unroll
                for (int j = 0; j < 4; j++) {
                    const int p = j >> 1, r = j & 1;
                    mma16816(acc[i][j], al, bh[p][r], bh[p][r + 2]);
                }
            }
        }
    };

    const int C = K >> 5;
    load_stage(0, 0); cp_commit();
    for (int c = 0; c < C; c++) {
        cp_wait<0>();
        __syncthreads();
        if (c + 1 < C) { load_stage((c + 1) & 1, c + 1); cp_commit(); }
        compute_stage(c & 1);
    }

    // epilogue
    const int mr = m0 + wm * 64;
    const int nc = n0 + wn * 32;
#pragma unroll
    for (int i = 0; i < 4; i++) {
#pragma unroll
        for (int j = 0; j < 4; j++) {
            int n = nc + j * 8 + tig * 2;
            float2 bv = *(const float2*)(bias + n);
            int r_lo = mr + i * 16 + gid;
            int r_hi = r_lo + 8;
            float v00 = acc[i][j][0] + bv.x, v01 = acc[i][j][1] + bv.y;
            float v10 = acc[i][j][2] + bv.x, v11 = acc[i][j][3] + bv.y;
            if (MODE == 1) {
                v00 = fmaxf(v00, 0.f); v01 = fmaxf(v01, 0.f);
                v10 = fmaxf(v10, 0.f); v11 = fmaxf(v11, 0.f);
                __nv_bfloat16 h00 = __float2bfloat16(v00), h01 = __float2bfloat16(v01);
                __nv_bfloat16 h10 = __float2bfloat16(v10), h11 = __float2bfloat16(v11);
                __nv_bfloat162 hi0(h00, h01), hi1(h10, h11);
                __nv_bfloat162 lo0(__float2bfloat16(v00 - __bfloat162float(h00)),
                                   __float2bfloat16(v01 - __bfloat162float(h01)));
                __nv_bfloat162 lo1(__float2bfloat16(v10 - __bfloat162float(h10)),
                                   __float2bfloat16(v11 - __bfloat162float(h11)));
                *(__nv_bfloat162*)(Chi + (size_t)r_lo * ldc + n) = hi0;
                *(__nv_bfloat162*)(Chi + (size_t)r_hi * ldc + n) = hi1;
                *(__nv_bfloat162*)(Clo + (size_t)r_lo * ldc + n) = lo0;
                *(__nv_bfloat162*)(Clo + (size_t)r_hi * ldc + n) = lo1;
            } else {
                *(float2*)(Cf + (size_t)r_lo * ldc + n) = make_float2(v00, v01);
                *(float2*)(Cf + (size_t)r_hi * ldc + n) = make_float2(v10, v11);
            }
        }
    }
}

// ---------------- convex fixed-point + gather (warp per row) ----------------
__global__ __launch_bounds__(256) void convex_gather(
    const float* __restrict__ p, const float* __restrict__ x, float* __restrict__ out) {
    const unsigned FULL = 0xffffffffu;
    int warp = (blockIdx.x * blockDim.x + threadIdx.x) >> 5;
    int lane = threadIdx.x & 31;
    if (warp >= BB) return;

    const float* row = p + (size_t)warp * NF;
    float e[8];
    {
        float4 v0 = *(const float4*)(row + lane * 8);
        float4 v1 = *(const float4*)(row + lane * 8 + 4);
        e[0] = v0.x; e[1] = v0.y; e[2] = v0.z; e[3] = v0.w;
        e[4] = v1.x; e[5] = v1.y; e[6] = v1.z; e[7] = v1.w;
    }
#pragma unroll 2
    for (int it = 0; it < 100; ++it) {
        float lin = __shfl_up_sync(FULL, e[7], 1);
        float rin = __shfl_down_sync(FULL, e[0], 1);
        float n0 = fminf(e[0], 0.5f * (lin + e[1]));
        float n1 = fminf(e[1], 0.5f * (e[0] + e[2]));
        float n2 = fminf(e[2], 0.5f * (e[1] + e[3]));
        float n3 = fminf(e[3], 0.5f * (e[2] + e[4]));
        float n4 = fminf(e[4], 0.5f * (e[3] + e[5]));
        float n5 = fminf(e[5], 0.5f * (e[4] + e[6]));
        float n6 = fminf(e[6], 0.5f * (e[5] + e[7]));
        float n7 = fminf(e[7], 0.5f * (e[6] + rin));
        if (lane == 0)  n0 = e[0];
        if (lane == 31) n7 = e[7];
        e[0] = n0; e[1] = n1; e[2] = n2; e[3] = n3;
        e[4] = n4; e[5] = n5; e[6] = n6; e[7] = n7;
    }
    float q = x[(size_t)warp * 257 + 256];
    int idx = (int)rintf(q * 255.0f);
    idx = min(max(idx, 0), 255);
    int src_lane = idx >> 3, sub = idx & 7;
    float val = 0.f;
#pragma unroll
    for (int j = 0; j < 8; j++) {
        float t = __shfl_sync(FULL, e[j], src_lane);
        if (j == sub) val = t;
    }
    if (lane == 0) out[warp] = val;
}

// ---------------- launch ----------------
extern "C" void kernel_launch(void* const* d_in, const int* in_sizes, int n_in,
                              void* d_out, int out_size) {
    const float* x  = (const float*)d_in[0];
    const float* W1 = (const float*)d_in[1];
    const float* b1 = (const float*)d_in[2];
    const float* W2 = (const float*)d_in[3];
    const float* b2 = (const float*)d_in[4];
    float* out = (float*)d_out;

    void *pa_hi, *pa_lo, *pw1h, *pw1l, *pw2h, *pw2l, *phh, *phl, *pp;
    cudaGetSymbolAddress(&pa_hi, g_a_hi); cudaGetSymbolAddress(&pa_lo, g_a_lo);
    cudaGetSymbolAddress(&pw1h, g_w1_hi); cudaGetSymbolAddress(&pw1l, g_w1_lo);
    cudaGetSymbolAddress(&pw2h, g_w2_hi); cudaGetSymbolAddress(&pw2l, g_w2_lo);
    cudaGetSymbolAddress(&phh, g_h_hi);   cudaGetSymbolAddress(&phl, g_h_lo);
    cudaGetSymbolAddress(&pp, g_p);

    __nv_bfloat16 *a_hi = (__nv_bfloat16*)pa_hi, *a_lo = (__nv_bfloat16*)pa_lo;
    __nv_bfloat16 *w1h = (__nv_bfloat16*)pw1h, *w1l = (__nv_bfloat16*)pw1l;
    __nv_bfloat16 *w2h = (__nv_bfloat16*)pw2h, *w2l = (__nv_bfloat16*)pw2l;
    __nv_bfloat16 *hh = (__nv_bfloat16*)phh, *hl = (__nv_bfloat16*)phl;
    float* prm = (float*)pp;

    cudaFuncSetAttribute(hmma_gemm<0>, cudaFuncAttributeMaxDynamicSharedMemorySize, SMEM_BYTES);
    cudaFuncSetAttribute(hmma_gemm<1>, cudaFuncAttributeMaxDynamicSharedMemorySize, SMEM_BYTES);

    split_x<<<BB * NI / 256, 256>>>(x, a_hi, a_lo);
    split_w<<<NH * NI / 256, 256>>>(W1, w1h, w1l, NH * NI);
    split_w<<<NF * NH / 256, 256>>>(W2, w2h, w2l, NF * NH);

    // GEMM1: h = relu(x @ W1^T + b1) -> bf16 hi/lo
    hmma_gemm<1><<<dim3(NH / 128, BB / 256), 512, SMEM_BYTES>>>(
        a_hi, a_lo, w1h, w1l, b1, NI, NH, nullptr, hh, hl);
    // GEMM2: prm = h @ W2^T + b2 (fp32)
    hmma_gemm<0><<<dim3(NF / 128, BB / 256), 512, SMEM_BYTES>>>(
        hh, hl, w2h, w2l, b2, NH, NF, prm, nullptr, nullptr);

    convex_gather<<<BB / 8, 256>>>(prm, x, out);
}

// round 10
// speedup vs baseline: 1.1487x; 1.1487x over previous
#include <cuda_runtime.h>
#include <cuda_bf16.h>
#include <cstdint>

#define BB 32768
#define NI 256
#define NH 1024
#define NF 256

// ---------------- scratch (device globals; no allocs allowed) ----------------
__device__ __align__(16) __nv_bfloat16 g_a_hi[(size_t)BB * NI];
__device__ __align__(16) __nv_bfloat16 g_a_lo[(size_t)BB * NI];
__device__ __align__(16) __nv_bfloat16 g_w1_hi[NH * NI];
__device__ __align__(16) __nv_bfloat16 g_w1_lo[NH * NI];
__device__ __align__(16) __nv_bfloat16 g_w2_hi[NF * NH];
__device__ __align__(16) __nv_bfloat16 g_w2_lo[NF * NH];
__device__ __align__(16) __nv_bfloat16 g_h_hi[(size_t)BB * NH];
__device__ __align__(16) __nv_bfloat16 g_h_lo[(size_t)BB * NH];
__device__ __align__(16) float g_p[(size_t)BB * NF];

__device__ __forceinline__ uint32_t smem_u32(const void* p) {
    uint32_t a;
    asm("{ .reg .u64 t; cvta.to.shared.u64 t, %1; cvt.u32.u64 %0, t; }" : "=r"(a) : "l"(p));
    return a;
}
__device__ __forceinline__ void cp16(uint32_t saddr, const void* gaddr) {
    asm volatile("cp.async.cg.shared.global [%0], [%1], 16;\n" :: "r"(saddr), "l"(gaddr));
}
__device__ __forceinline__ void cp_commit() {
    asm volatile("cp.async.commit_group;\n" ::: "memory");
}
template <int N>
__device__ __forceinline__ void cp_wait() {
    asm volatile("cp.async.wait_group %0;\n" :: "n"(N) : "memory");
}
__device__ __forceinline__ void ldmx4(uint32_t* r, uint32_t addr) {
    asm volatile("ldmatrix.sync.aligned.m8n8.x4.shared.b16 {%0,%1,%2,%3}, [%4];"
                 : "=r"(r[0]), "=r"(r[1]), "=r"(r[2]), "=r"(r[3]) : "r"(addr));
}
__device__ __forceinline__ void mma16816(float* d, const uint32_t* a, uint32_t b0, uint32_t b1) {
    asm volatile(
        "mma.sync.aligned.m16n8k16.row.col.f32.bf16.bf16.f32 "
        "{%0,%1,%2,%3}, {%4,%5,%6,%7}, {%8,%9}, {%0,%1,%2,%3};"
        : "+f"(d[0]), "+f"(d[1]), "+f"(d[2]), "+f"(d[3])
        : "r"(a[0]), "r"(a[1]), "r"(a[2]), "r"(a[3]), "r"(b0), "r"(b1));
}

// ---------------- hi/lo split kernels ----------------
__global__ __launch_bounds__(256) void split_x(const float* __restrict__ x,
                                               __nv_bfloat16* __restrict__ hi,
                                               __nv_bfloat16* __restrict__ lo) {
    int i = blockIdx.x * 256 + threadIdx.x;           // i < BB*NI
    int r = i >> 8, c = i & 255;
    float v = x[(size_t)r * 257 + c];
    __nv_bfloat16 h = __float2bfloat16(v);
    hi[i] = h;
    lo[i] = __float2bfloat16(v - __bfloat162float(h));
}
__global__ __launch_bounds__(256) void split_w(const float* __restrict__ w,
                                               __nv_bfloat16* __restrict__ hi,
                                               __nv_bfloat16* __restrict__ lo, int n) {
    int i = blockIdx.x * 256 + threadIdx.x;
    if (i < n) {
        float v = w[i];
        __nv_bfloat16 h = __float2bfloat16(v);
        hi[i] = h;
        lo[i] = __float2bfloat16(v - __bfloat162float(h));
    }
}

// ---------------- HMMA GEMM (mma.sync m16n8k16 bf16, 3-pass hi/lo) ----------
// C[M,N] = A[M,K] @ B[N,K]^T + bias.  CTA tile 128x128x32, 8 warps (2x4),
// warp tile 64x32.  3-stage cp.async pipeline (wait<1>), 2 CTAs/SM.
// Unpadded 64B rows with chunk swizzle: phys_chunk = chunk ^ ((row>>1)&3)
// (conflict-free for both the STS fills and all ldmatrix phases; the
//  XOR term is invariant under 16-row tile offsets so it is one per-lane const).
// MODE 0: fp32 out.  MODE 1: relu + bf16 hi/lo out.
constexpr int ROWB   = 64;                  // bytes per row (32 bf16, no pad)
constexpr int TILE   = 128 * ROWB;          // 8192 B per tensor
constexpr int STAGE  = 4 * TILE;            // 32768 B (Ah,Al,Bh,Bl)
constexpr int SMEM_BYTES = 3 * STAGE;       // 98304 B -> 2 CTAs/SM

template <int MODE>
__global__ __launch_bounds__(256, 2) void hmma_gemm(
    const __nv_bfloat16* __restrict__ Ah, const __nv_bfloat16* __restrict__ Al,
    const __nv_bfloat16* __restrict__ Bh, const __nv_bfloat16* __restrict__ Bl,
    const float* __restrict__ bias, int K, int ldc,
    float* __restrict__ Cf,
    __nv_bfloat16* __restrict__ Chi, __nv_bfloat16* __restrict__ Clo)
{
    extern __shared__ __align__(128) char smem[];
    const uint32_t sb = smem_u32(smem);
    const int tid = threadIdx.x;
    const int w = tid >> 5, lane = tid & 31;
    const int wm = w >> 2, wn = w & 3;        // 2x4 warp grid
    const int gid = lane >> 2, tig = lane & 3;
    const int m0 = blockIdx.y * 128, n0 = blockIdx.x * 128;

    float acc[4][4][4];
#pragma unroll
    for (int i = 0; i < 4; i++)
#pragma unroll
        for (int j = 0; j < 4; j++)
#pragma unroll
            for (int t = 0; t < 4; t++) acc[i][j][t] = 0.f;

    // loader mapping: idx = tid + 256*t (t=0,1) -> row=idx>>2 (0..127), ch=idx&3
    auto load_stage = [&](int s, int c) {
        const uint32_t st = sb + s * STAGE;
        const int k0 = c * 32;
#pragma unroll
        for (int t = 0; t < 2; t++) {
            int idx = tid + t * 256;
            int row = idx >> 2, ch = idx & 3;
            int chp = ch ^ ((row >> 1) & 3);
            uint32_t so = st + row * ROWB + chp * 16;
            size_t goffA = (size_t)(m0 + row) * K + k0 + ch * 8;
            size_t goffB = (size_t)(n0 + row) * K + k0 + ch * 8;
            cp16(so,            Ah + goffA);
            cp16(so + TILE,     Al + goffA);
            cp16(so + 2 * TILE, Bh + goffB);
            cp16(so + 3 * TILE, Bl + goffB);
        }
    };

    const uint32_t lsel = (lane & 15), hsel = (lane >> 4);
    const uint32_t xr = (lsel >> 1) & 3;    // swizzle const (invariant over tiles)

    auto compute_stage = [&](int s) {
        const uint32_t st = sb + s * STAGE;
#pragma unroll
        for (int ks = 0; ks < 2; ks++) {
            uint32_t chp = ((uint32_t)(ks * 2) + hsel) ^ xr;
            uint32_t a_off = st + (wm * 64 + lsel) * ROWB + chp * 16;
            uint32_t b_off = st + 2 * TILE + (wn * 32 + lsel) * ROWB + chp * 16;
            uint32_t bh[2][4], bl[2][4];
#pragma unroll
            for (int p = 0; p < 2; p++) ldmx4(bh[p], b_off + p * 16 * ROWB);
#pragma unroll
            for (int p = 0; p < 2; p++) ldmx4(bl[p], b_off + p * 16 * ROWB + TILE);
#pragma unroll
            for (int i = 0; i < 4; i++) {
                uint32_t ah[4], al[4];
                ldmx4(ah, a_off + i * 16 * ROWB);
                ldmx4(al, a_off + i * 16 * ROWB + TILE);
#pragma unroll
                for (int j = 0; j < 4; j++) {
                    const int p = j >> 1, r = j & 1;
                    mma16816(acc[i][j], ah, bh[p][r], bh[p][r + 2]);
                }
#pragma unroll
                for (int j = 0; j < 4; j++) {
                    const int p = j >> 1, r = j & 1;
                    mma16816(acc[i][j], ah, bl[p][r], bl[p][r + 2]);
                }
#pragma unroll
                for (int j = 0; j < 4; j++) {
                    const int p = j >> 1, r = j & 1;
                    mma16816(acc[i][j], al, bh[p][r], bh[p][r + 2]);
                }
            }
        }
    };

    const int C = K >> 5;
    load_stage(0, 0); cp_commit();
    load_stage(1, 1); cp_commit();
    for (int c = 0; c < C; c++) {
        if (c + 1 < C) cp_wait<1>(); else cp_wait<0>();
        __syncthreads();
        if (c + 2 < C) { load_stage((c + 2) % 3, c + 2); cp_commit(); }
        compute_stage(c % 3);
    }

    // epilogue
    const int mr = m0 + wm * 64;
    const int nc = n0 + wn * 32;
#pragma unroll
    for (int i = 0; i < 4; i++) {
#pragma unroll
        for (int j = 0; j < 4; j++) {
            int n = nc + j * 8 + tig * 2;
            float2 bv = *(const float2*)(bias + n);
            int r_lo = mr + i * 16 + gid;
            int r_hi = r_lo + 8;
            float v00 = acc[i][j][0] + bv.x, v01 = acc[i][j][1] + bv.y;
            float v10 = acc[i][j][2] + bv.x, v11 = acc[i][j][3] + bv.y;
            if (MODE == 1) {
                v00 = fmaxf(v00, 0.f); v01 = fmaxf(v01, 0.f);
                v10 = fmaxf(v10, 0.f); v11 = fmaxf(v11, 0.f);
                __nv_bfloat16 h00 = __float2bfloat16(v00), h01 = __float2bfloat16(v01);
                __nv_bfloat16 h10 = __float2bfloat16(v10), h11 = __float2bfloat16(v11);
                __nv_bfloat162 hi0(h00, h01), hi1(h10, h11);
                __nv_bfloat162 lo0(__float2bfloat16(v00 - __bfloat162float(h00)),
                                   __float2bfloat16(v01 - __bfloat162float(h01)));
                __nv_bfloat162 lo1(__float2bfloat16(v10 - __bfloat162float(h10)),
                                   __float2bfloat16(v11 - __bfloat162float(h11)));
                *(__nv_bfloat162*)(Chi + (size_t)r_lo * ldc + n) = hi0;
                *(__nv_bfloat162*)(Chi + (size_t)r_hi * ldc + n) = hi1;
                *(__nv_bfloat162*)(Clo + (size_t)r_lo * ldc + n) = lo0;
                *(__nv_bfloat162*)(Clo + (size_t)r_hi * ldc + n) = lo1;
            } else {
                *(float2*)(Cf + (size_t)r_lo * ldc + n) = make_float2(v00, v01);
                *(float2*)(Cf + (size_t)r_hi * ldc + n) = make_float2(v10, v11);
            }
        }
    }
}

// ---------------- convex fixed-point + gather (warp per row) ----------------
__global__ __launch_bounds__(256) void convex_gather(
    const float* __restrict__ p, const float* __restrict__ x, float* __restrict__ out) {
    const unsigned FULL = 0xffffffffu;
    int warp = (blockIdx.x * blockDim.x + threadIdx.x) >> 5;
    int lane = threadIdx.x & 31;
    if (warp >= BB) return;

    const float* row = p + (size_t)warp * NF;
    float e[8];
    {
        float4 v0 = *(const float4*)(row + lane * 8);
        float4 v1 = *(const float4*)(row + lane * 8 + 4);
        e[0] = v0.x; e[1] = v0.y; e[2] = v0.z; e[3] = v0.w;
        e[4] = v1.x; e[5] = v1.y; e[6] = v1.z; e[7] = v1.w;
    }
#pragma unroll 2
    for (int it = 0; it < 100; ++it) {
        float lin = __shfl_up_sync(FULL, e[7], 1);
        float rin = __shfl_down_sync(FULL, e[0], 1);
        float n0 = fminf(e[0], 0.5f * (lin + e[1]));
        float n1 = fminf(e[1], 0.5f * (e[0] + e[2]));
        float n2 = fminf(e[2], 0.5f * (e[1] + e[3]));
        float n3 = fminf(e[3], 0.5f * (e[2] + e[4]));
        float n4 = fminf(e[4], 0.5f * (e[3] + e[5]));
        float n5 = fminf(e[5], 0.5f * (e[4] + e[6]));
        float n6 = fminf(e[6], 0.5f * (e[5] + e[7]));
        float n7 = fminf(e[7], 0.5f * (e[6] + rin));
        if (lane == 0)  n0 = e[0];
        if (lane == 31) n7 = e[7];
        e[0] = n0; e[1] = n1; e[2] = n2; e[3] = n3;
        e[4] = n4; e[5] = n5; e[6] = n6; e[7] = n7;
    }
    float q = x[(size_t)warp * 257 + 256];
    int idx = (int)rintf(q * 255.0f);
    idx = min(max(idx, 0), 255);
    int src_lane = idx >> 3, sub = idx & 7;
    float val = 0.f;
#pragma unroll
    for (int j = 0; j < 8; j++) {
        float t = __shfl_sync(FULL, e[j], src_lane);
        if (j == sub) val = t;
    }
    if (lane == 0) out[warp] = val;
}

// ---------------- launch ----------------
extern "C" void kernel_launch(void* const* d_in, const int* in_sizes, int n_in,
                              void* d_out, int out_size) {
    const float* x  = (const float*)d_in[0];
    const float* W1 = (const float*)d_in[1];
    const float* b1 = (const float*)d_in[2];
    const float* W2 = (const float*)d_in[3];
    const float* b2 = (const float*)d_in[4];
    float* out = (float*)d_out;

    void *pa_hi, *pa_lo, *pw1h, *pw1l, *pw2h, *pw2l, *phh, *phl, *pp;
    cudaGetSymbolAddress(&pa_hi, g_a_hi); cudaGetSymbolAddress(&pa_lo, g_a_lo);
    cudaGetSymbolAddress(&pw1h, g_w1_hi); cudaGetSymbolAddress(&pw1l, g_w1_lo);
    cudaGetSymbolAddress(&pw2h, g_w2_hi); cudaGetSymbolAddress(&pw2l, g_w2_lo);
    cudaGetSymbolAddress(&phh, g_h_hi);   cudaGetSymbolAddress(&phl, g_h_lo);
    cudaGetSymbolAddress(&pp, g_p);

    __nv_bfloat16 *a_hi = (__nv_bfloat16*)pa_hi, *a_lo = (__nv_bfloat16*)pa_lo;
    __nv_bfloat16 *w1h = (__nv_bfloat16*)pw1h, *w1l = (__nv_bfloat16*)pw1l;
    __nv_bfloat16 *w2h = (__nv_bfloat16*)pw2h, *w2l = (__nv_bfloat16*)pw2l;
    __nv_bfloat16 *hh = (__nv_bfloat16*)phh, *hl = (__nv_bfloat16*)phl;
    float* prm = (float*)pp;

    cudaFuncSetAttribute(hmma_gemm<0>, cudaFuncAttributeMaxDynamicSharedMemorySize, SMEM_BYTES);
    cudaFuncSetAttribute(hmma_gemm<1>, cudaFuncAttributeMaxDynamicSharedMemorySize, SMEM_BYTES);

    split_x<<<BB * NI / 256, 256>>>(x, a_hi, a_lo);
    split_w<<<NH * NI / 256, 256>>>(W1, w1h, w1l, NH * NI);
    split_w<<<NF * NH / 256, 256>>>(W2, w2h, w2l, NF * NH);

    // GEMM1: h = relu(x @ W1^T + b1) -> bf16 hi/lo
    hmma_gemm<1><<<dim3(NH / 128, BB / 128), 256, SMEM_BYTES>>>(
        a_hi, a_lo, w1h, w1l, b1, NI, NH, nullptr, hh, hl);
    // GEMM2: prm = h @ W2^T + b2 (fp32)
    hmma_gemm<0><<<dim3(NF / 128, BB / 128), 256, SMEM_BYTES>>>(
        hh, hl, w2h, w2l, b2, NH, NF, prm, nullptr, nullptr);

    convex_gather<<<BB / 8, 256>>>(prm, x, out);
}

// round 12
// speedup vs baseline: 1.1677x; 1.0166x over previous
#include <cuda_runtime.h>
#include <cuda_bf16.h>
#include <cstdint>

#define BB 32768
#define NI 256
#define NH 1024
#define NF 256

// ---------------- scratch (device globals; no allocs allowed) ----------------
__device__ __align__(16) __nv_bfloat16 g_a_hi[(size_t)BB * NI];
__device__ __align__(16) __nv_bfloat16 g_a_lo[(size_t)BB * NI];
__device__ __align__(16) __nv_bfloat16 g_w1_hi[NH * NI];
__device__ __align__(16) __nv_bfloat16 g_w1_lo[NH * NI];
__device__ __align__(16) __nv_bfloat16 g_w2_hi[NF * NH];
__device__ __align__(16) __nv_bfloat16 g_w2_lo[NF * NH];
__device__ __align__(16) __nv_bfloat16 g_h_hi[(size_t)BB * NH];
__device__ __align__(16) __nv_bfloat16 g_h_lo[(size_t)BB * NH];
__device__ __align__(16) float g_p[(size_t)BB * NF];

__device__ __forceinline__ uint32_t smem_u32(const void* p) {
    uint32_t a;
    asm("{ .reg .u64 t; cvta.to.shared.u64 t, %1; cvt.u32.u64 %0, t; }" : "=r"(a) : "l"(p));
    return a;
}
__device__ __forceinline__ void cp16(uint32_t saddr, const void* gaddr) {
    asm volatile("cp.async.cg.shared.global [%0], [%1], 16;\n" :: "r"(saddr), "l"(gaddr));
}
__device__ __forceinline__ void ldmx4(uint32_t* r, uint32_t addr) {
    asm volatile("ldmatrix.sync.aligned.m8n8.x4.shared.b16 {%0,%1,%2,%3}, [%4];"
                 : "=r"(r[0]), "=r"(r[1]), "=r"(r[2]), "=r"(r[3]) : "r"(addr));
}
__device__ __forceinline__ void mma16816(float* d, const uint32_t* a, uint32_t b0, uint32_t b1) {
    asm volatile(
        "mma.sync.aligned.m16n8k16.row.col.f32.bf16.bf16.f32 "
        "{%0,%1,%2,%3}, {%4,%5,%6,%7}, {%8,%9}, {%0,%1,%2,%3};"
        : "+f"(d[0]), "+f"(d[1]), "+f"(d[2]), "+f"(d[3])
        : "r"(a[0]), "r"(a[1]), "r"(a[2]), "r"(a[3]), "r"(b0), "r"(b1));
}
#define MBAR_INIT(mb, n)  asm volatile("mbarrier.init.shared.b64 [%0], %1;" :: "r"(mb), "r"(n) : "memory")
__device__ __forceinline__ void mbar_wait(uint32_t mb, uint32_t parity) {
    uint32_t done;
    asm volatile(
        "{\n\t.reg .pred p;\n\t"
        "mbarrier.try_wait.parity.acquire.cta.shared::cta.b64 p, [%1], %2;\n\t"
        "selp.b32 %0, 1, 0, p;\n\t}"
        : "=r"(done) : "r"(mb), "r"(parity) : "memory");
    if (!done) {
        asm volatile(
            "{\n\t.reg .pred P1;\n\t"
            "WL_%=:\n\t"
            "mbarrier.try_wait.parity.acquire.cta.shared::cta.b64 P1, [%0], %1, 0x989680;\n\t"
            "@P1 bra.uni WD_%=;\n\t"
            "bra.uni WL_%=;\n\t"
            "WD_%=:\n\t}"
            :: "r"(mb), "r"(parity) : "memory");
    }
}

// ---------------- hi/lo split kernels ----------------
__global__ __launch_bounds__(256) void split_x(const float* __restrict__ x,
                                               __nv_bfloat16* __restrict__ hi,
                                               __nv_bfloat16* __restrict__ lo) {
    int i = blockIdx.x * 256 + threadIdx.x;           // i < BB*NI
    int r = i >> 8, c = i & 255;
    float v = x[(size_t)r * 257 + c];
    __nv_bfloat16 h = __float2bfloat16(v);
    hi[i] = h;
    lo[i] = __float2bfloat16(v - __bfloat162float(h));
}
__global__ __launch_bounds__(256) void split_w(const float* __restrict__ w,
                                               __nv_bfloat16* __restrict__ hi,
                                               __nv_bfloat16* __restrict__ lo, int n) {
    int i = blockIdx.x * 256 + threadIdx.x;
    if (i < n) {
        float v = w[i];
        __nv_bfloat16 h = __float2bfloat16(v);
        hi[i] = h;
        lo[i] = __float2bfloat16(v - __bfloat162float(h));
    }
}

// ---------------- HMMA GEMM (mma.sync m16n8k16 bf16, 3-pass hi/lo) ----------
// C[M,N] = A[M,K] @ B[N,K]^T + bias.  CTA tile 256x128x32, 16 warps (4x4),
// warp tile 64x32, 512 threads, 1 CTA/SM.
// 4-stage cp.async ring with mbarrier full/empty pairs (cp.async.mbarrier.
// arrive.NOINC so arrivals count against the preset 512); NO __syncthreads
// in the main loop - warps free-run with up to a stage of skew.
// Unpadded 64B rows, chunk XOR swizzle.
// MODE 0: fp32 out.  MODE 1: relu + bf16 hi/lo out.
constexpr int NST    = 4;
constexpr int ROWB   = 64;                   // bytes per row (32 bf16)
constexpr int A_T    = 256 * ROWB;           // 16384 B per A tensor
constexpr int B_T    = 128 * ROWB;           // 8192 B per B tensor
constexpr int STAGE  = 2 * A_T + 2 * B_T;    // 49152 B
constexpr int SMEM_MAIN  = NST * STAGE;      // 196608 B
constexpr int SMEM_BYTES = SMEM_MAIN + 128;  // + mbarriers

template <int MODE>
__global__ __launch_bounds__(512, 1) void hmma_gemm(
    const __nv_bfloat16* __restrict__ Ah, const __nv_bfloat16* __restrict__ Al,
    const __nv_bfloat16* __restrict__ Bh, const __nv_bfloat16* __restrict__ Bl,
    const float* __restrict__ bias, int K, int ldc,
    float* __restrict__ Cf,
    __nv_bfloat16* __restrict__ Chi, __nv_bfloat16* __restrict__ Clo)
{
    extern __shared__ __align__(128) char smem[];
    const uint32_t sb = smem_u32(smem);
    const int tid = threadIdx.x;
    const int w = tid >> 5, lane = tid & 31;
    const int wm = w >> 2, wn = w & 3;        // 4x4 warp grid
    const int gid = lane >> 2, tig = lane & 3;
    const int m0 = blockIdx.y * 256, n0 = blockIdx.x * 128;
    const uint32_t mb_full  = sb + SMEM_MAIN;        // 4 x 8B
    const uint32_t mb_empty = sb + SMEM_MAIN + 64;   // 4 x 8B

    if (tid < NST) {
        MBAR_INIT(mb_full  + tid * 8, 512);   // one noinc cp-arrive per thread
        MBAR_INIT(mb_empty + tid * 8, 16);    // one arrive per warp
    }
    __syncthreads();

    float acc[4][4][4];
#pragma unroll
    for (int i = 0; i < 4; i++)
#pragma unroll
        for (int j = 0; j < 4; j++)
#pragma unroll
            for (int t = 0; t < 4; t++) acc[i][j][t] = 0.f;

    auto load_stage = [&](int s, int c) {
        const uint32_t st = sb + s * STAGE;
        const int k0 = c * 32;
        // A: 256 rows x 4 chunks, 2 per thread
#pragma unroll
        for (int t = 0; t < 2; t++) {
            int idx = tid + t * 512;
            int row = idx >> 2, ch = idx & 3;
            int chp = ch ^ ((row >> 1) & 3);
            uint32_t so = st + row * ROWB + chp * 16;
            size_t g = (size_t)(m0 + row) * K + k0 + ch * 8;
            cp16(so,       Ah + g);
            cp16(so + A_T, Al + g);
        }
        // B: 128 rows x 4 chunks, 1 per thread
        {
            int row = tid >> 2, ch = tid & 3;
            int chp = ch ^ ((row >> 1) & 3);
            uint32_t so = st + 2 * A_T + row * ROWB + chp * 16;
            size_t g = (size_t)(n0 + row) * K + k0 + ch * 8;
            cp16(so,       Bh + g);
            cp16(so + B_T, Bl + g);
        }
        asm volatile("cp.async.mbarrier.arrive.noinc.shared::cta.b64 [%0];"
                     :: "r"(mb_full + s * 8) : "memory");
    };

    const uint32_t lsel = (lane & 15), hsel = (lane >> 4);
    const uint32_t xr = (lsel >> 1) & 3;

    auto compute_stage = [&](int s) {
        const uint32_t st = sb + s * STAGE;
#pragma unroll
        for (int ks = 0; ks < 2; ks++) {
            uint32_t chp = ((uint32_t)(ks * 2) + hsel) ^ xr;
            uint32_t a_off = st + (wm * 64 + lsel) * ROWB + chp * 16;
            uint32_t b_off = st + 2 * A_T + (wn * 32 + lsel) * ROWB + chp * 16;
            uint32_t bh[2][4], bl[2][4];
#pragma unroll
            for (int p = 0; p < 2; p++) ldmx4(bh[p], b_off + p * 16 * ROWB);
#pragma unroll
            for (int p = 0; p < 2; p++) ldmx4(bl[p], b_off + p * 16 * ROWB + B_T);
#pragma unroll
            for (int i = 0; i < 4; i++) {
                uint32_t ah[4], al[4];
                ldmx4(ah, a_off + i * 16 * ROWB);
                ldmx4(al, a_off + i * 16 * ROWB + A_T);
#pragma unroll
                for (int j = 0; j < 4; j++) {
                    const int p = j >> 1, r = j & 1;
                    mma16816(acc[i][j], ah, bh[p][r], bh[p][r + 2]);
                }
#pragma unroll
                for (int j = 0; j < 4; j++) {
                    const int p = j >> 1, r = j & 1;
                    mma16816(acc[i][j], ah, bl[p][r], bl[p][r + 2]);
                }
#pragma unroll
                for (int j = 0; j < 4; j++) {
                    const int p = j >> 1, r = j & 1;
                    mma16816(acc[i][j], al, bh[p][r], bh[p][r + 2]);
                }
            }
        }
    };

    const int C = K >> 5;
#pragma unroll
    for (int s = 0; s < NST - 1; s++) load_stage(s, s);   // c = 0,1,2
    for (int c = 0; c < C; c++) {
        const int s = c & 3;
        mbar_wait(mb_full + s * 8, (c >> 2) & 1);
        compute_stage(s);
        if (lane == 0)
            asm volatile("mbarrier.arrive.release.cta.shared::cta.b64 _, [%0];"
                         :: "r"(mb_empty + s * 8) : "memory");
        const int cn = c + NST - 1;
        if (cn < C) {
            const int sn = cn & 3, k = cn >> 2;
            if (k >= 1) mbar_wait(mb_empty + sn * 8, (k - 1) & 1);
            load_stage(sn, cn);
        }
    }

    // epilogue
    const int mr = m0 + wm * 64;
    const int nc = n0 + wn * 32;
#pragma unroll
    for (int i = 0; i < 4; i++) {
#pragma unroll
        for (int j = 0; j < 4; j++) {
            int n = nc + j * 8 + tig * 2;
            float2 bv = *(const float2*)(bias + n);
            int r_lo = mr + i * 16 + gid;
            int r_hi = r_lo + 8;
            float v00 = acc[i][j][0] + bv.x, v01 = acc[i][j][1] + bv.y;
            float v10 = acc[i][j][2] + bv.x, v11 = acc[i][j][3] + bv.y;
            if (MODE == 1) {
                v00 = fmaxf(v00, 0.f); v01 = fmaxf(v01, 0.f);
                v10 = fmaxf(v10, 0.f); v11 = fmaxf(v11, 0.f);
                __nv_bfloat16 h00 = __float2bfloat16(v00), h01 = __float2bfloat16(v01);
                __nv_bfloat16 h10 = __float2bfloat16(v10), h11 = __float2bfloat16(v11);
                __nv_bfloat162 hi0(h00, h01), hi1(h10, h11);
                __nv_bfloat162 lo0(__float2bfloat16(v00 - __bfloat162float(h00)),
                                   __float2bfloat16(v01 - __bfloat162float(h01)));
                __nv_bfloat162 lo1(__float2bfloat16(v10 - __bfloat162float(h10)),
                                   __float2bfloat16(v11 - __bfloat162float(h11)));
                *(__nv_bfloat162*)(Chi + (size_t)r_lo * ldc + n) = hi0;
                *(__nv_bfloat162*)(Chi + (size_t)r_hi * ldc + n) = hi1;
                *(__nv_bfloat162*)(Clo + (size_t)r_lo * ldc + n) = lo0;
                *(__nv_bfloat162*)(Clo + (size_t)r_hi * ldc + n) = lo1;
            } else {
                *(float2*)(Cf + (size_t)r_lo * ldc + n) = make_float2(v00, v01);
                *(float2*)(Cf + (size_t)r_hi * ldc + n) = make_float2(v10, v11);
            }
        }
    }
}

// ---------------- convex fixed-point + gather (warp per row) ----------------
__global__ __launch_bounds__(256) void convex_gather(
    const float* __restrict__ p, const float* __restrict__ x, float* __restrict__ out) {
    const unsigned FULL = 0xffffffffu;
    int warp = (blockIdx.x * blockDim.x + threadIdx.x) >> 5;
    int lane = threadIdx.x & 31;
    if (warp >= BB) return;

    const float* row = p + (size_t)warp * NF;
    float e[8];
    {
        float4 v0 = *(const float4*)(row + lane * 8);
        float4 v1 = *(const float4*)(row + lane * 8 + 4);
        e[0] = v0.x; e[1] = v0.y; e[2] = v0.z; e[3] = v0.w;
        e[4] = v1.x; e[5] = v1.y; e[6] = v1.z; e[7] = v1.w;
    }
#pragma unroll 2
    for (int it = 0; it < 100; ++it) {
        float lin = __shfl_up_sync(FULL, e[7], 1);
        float rin = __shfl_down_sync(FULL, e[0], 1);
        float n0 = fminf(e[0], 0.5f * (lin + e[1]));
        float n1 = fminf(e[1], 0.5f * (e[0] + e[2]));
        float n2 = fminf(e[2], 0.5f * (e[1] + e[3]));
        float n3 = fminf(e[3], 0.5f * (e[2] + e[4]));
        float n4 = fminf(e[4], 0.5f * (e[3] + e[5]));
        float n5 = fminf(e[5], 0.5f * (e[4] + e[6]));
        float n6 = fminf(e[6], 0.5f * (e[5] + e[7]));
        float n7 = fminf(e[7], 0.5f * (e[6] + rin));
        if (lane == 0)  n0 = e[0];
        if (lane == 31) n7 = e[7];
        e[0] = n0; e[1] = n1; e[2] = n2; e[3] = n3;
        e[4] = n4; e[5] = n5; e[6] = n6; e[7] = n7;
    }
    float q = x[(size_t)warp * 257 + 256];
    int idx = (int)rintf(q * 255.0f);
    idx = min(max(idx, 0), 255);
    int src_lane = idx >> 3, sub = idx & 7;
    float val = 0.f;
#pragma unroll
    for (int j = 0; j < 8; j++) {
        float t = __shfl_sync(FULL, e[j], src_lane);
        if (j == sub) val = t;
    }
    if (lane == 0) out[warp] = val;
}

// ---------------- launch ----------------
extern "C" void kernel_launch(void* const* d_in, const int* in_sizes, int n_in,
                              void* d_out, int out_size) {
    const float* x  = (const float*)d_in[0];
    const float* W1 = (const float*)d_in[1];
    const float* b1 = (const float*)d_in[2];
    const float* W2 = (const float*)d_in[3];
    const float* b2 = (const float*)d_in[4];
    float* out = (float*)d_out;

    void *pa_hi, *pa_lo, *pw1h, *pw1l, *pw2h, *pw2l, *phh, *phl, *pp;
    cudaGetSymbolAddress(&pa_hi, g_a_hi); cudaGetSymbolAddress(&pa_lo, g_a_lo);
    cudaGetSymbolAddress(&pw1h, g_w1_hi); cudaGetSymbolAddress(&pw1l, g_w1_lo);
    cudaGetSymbolAddress(&pw2h, g_w2_hi); cudaGetSymbolAddress(&pw2l, g_w2_lo);
    cudaGetSymbolAddress(&phh, g_h_hi);   cudaGetSymbolAddress(&phl, g_h_lo);
    cudaGetSymbolAddress(&pp, g_p);

    __nv_bfloat16 *a_hi = (__nv_bfloat16*)pa_hi, *a_lo = (__nv_bfloat16*)pa_lo;
    __nv_bfloat16 *w1h = (__nv_bfloat16*)pw1h, *w1l = (__nv_bfloat16*)pw1l;
    __nv_bfloat16 *w2h = (__nv_bfloat16*)pw2h, *w2l = (__nv_bfloat16*)pw2l;
    __nv_bfloat16 *hh = (__nv_bfloat16*)phh, *hl = (__nv_bfloat16*)phl;
    float* prm = (float*)pp;

    cudaFuncSetAttribute(hmma_gemm<0>, cudaFuncAttributeMaxDynamicSharedMemorySize, SMEM_BYTES);
    cudaFuncSetAttribute(hmma_gemm<1>, cudaFuncAttributeMaxDynamicSharedMemorySize, SMEM_BYTES);

    split_x<<<BB * NI / 256, 256>>>(x, a_hi, a_lo);
    split_w<<<NH * NI / 256, 256>>>(W1, w1h, w1l, NH * NI);
    split_w<<<NF * NH / 256, 256>>>(W2, w2h, w2l, NF * NH);

    // GEMM1: h = relu(x @ W1^T + b1) -> bf16 hi/lo
    hmma_gemm<1><<<dim3(NH / 128, BB / 256), 512, SMEM_BYTES>>>(
        a_hi, a_lo, w1h, w1l, b1, NI, NH, nullptr, hh, hl);
    // GEMM2: prm = h @ W2^T + b2 (fp32)
    hmma_gemm<0><<<dim3(NF / 128, BB / 256), 512, SMEM_BYTES>>>(
        hh, hl, w2h, w2l, b2, NH, NF, prm, nullptr, nullptr);

    convex_gather<<<BB / 8, 256>>>(prm, x, out);
}

// round 13
// speedup vs baseline: 2.0453x; 1.7515x over previous
#include <cuda_runtime.h>
#include <cuda_fp16.h>
#include <cstdint>

#define BB 32768
#define NI 256
#define NH 1024
#define NF 256

// ---------------- scratch (device globals; no allocs allowed) ----------------
__device__ __align__(16) __half g_a[(size_t)BB * NI];    // x as fp16
__device__ __align__(16) __half g_w1[NH * NI];           // W1 as fp16
__device__ __align__(16) __half g_w2[NF * NH];           // W2 as fp16
__device__ __align__(16) __half g_h[(size_t)BB * NH];    // hidden as fp16
__device__ __align__(16) float  g_p[(size_t)BB * NF];    // param fp32

__device__ __forceinline__ uint32_t smem_u32(const void* p) {
    uint32_t a;
    asm("{ .reg .u64 t; cvta.to.shared.u64 t, %1; cvt.u32.u64 %0, t; }" : "=r"(a) : "l"(p));
    return a;
}
__device__ __forceinline__ void cp16(uint32_t saddr, const void* gaddr) {
    asm volatile("cp.async.cg.shared.global [%0], [%1], 16;\n" :: "r"(saddr), "l"(gaddr));
}
__device__ __forceinline__ void ldmx4(uint32_t* r, uint32_t addr) {
    asm volatile("ldmatrix.sync.aligned.m8n8.x4.shared.b16 {%0,%1,%2,%3}, [%4];"
                 : "=r"(r[0]), "=r"(r[1]), "=r"(r[2]), "=r"(r[3]) : "r"(addr));
}
__device__ __forceinline__ void mma16816(float* d, const uint32_t* a, uint32_t b0, uint32_t b1) {
    asm volatile(
        "mma.sync.aligned.m16n8k16.row.col.f32.f16.f16.f32 "
        "{%0,%1,%2,%3}, {%4,%5,%6,%7}, {%8,%9}, {%0,%1,%2,%3};"
        : "+f"(d[0]), "+f"(d[1]), "+f"(d[2]), "+f"(d[3])
        : "r"(a[0]), "r"(a[1]), "r"(a[2]), "r"(a[3]), "r"(b0), "r"(b1));
}
#define MBAR_INIT(mb, n)  asm volatile("mbarrier.init.shared.b64 [%0], %1;" :: "r"(mb), "r"(n) : "memory")
__device__ __forceinline__ void mbar_wait(uint32_t mb, uint32_t parity) {
    uint32_t done;
    asm volatile(
        "{\n\t.reg .pred p;\n\t"
        "mbarrier.try_wait.parity.acquire.cta.shared::cta.b64 p, [%1], %2;\n\t"
        "selp.b32 %0, 1, 0, p;\n\t}"
        : "=r"(done) : "r"(mb), "r"(parity) : "memory");
    if (!done) {
        asm volatile(
            "{\n\t.reg .pred P1;\n\t"
            "WL_%=:\n\t"
            "mbarrier.try_wait.parity.acquire.cta.shared::cta.b64 P1, [%0], %1, 0x989680;\n\t"
            "@P1 bra.uni WD_%=;\n\t"
            "bra.uni WL_%=;\n\t"
            "WD_%=:\n\t}"
            :: "r"(mb), "r"(parity) : "memory");
    }
}

// ---------------- fp16 convert kernels ----------------
__global__ __launch_bounds__(256) void conv_x(const float* __restrict__ x,
                                              __half* __restrict__ o) {
    int i = blockIdx.x * 256 + threadIdx.x;           // i < BB*NI
    int r = i >> 8, c = i & 255;
    o[i] = __float2half(x[(size_t)r * 257 + c]);
}
__global__ __launch_bounds__(256) void conv_w(const float* __restrict__ w,
                                              __half* __restrict__ o, int n) {
    int i = blockIdx.x * 256 + threadIdx.x;
    if (i < n) o[i] = __float2half(w[i]);
}

// ---------------- HMMA GEMM (mma.sync m16n8k16 fp16, single pass) ----------
// C[M,N] = A[M,K] @ B[N,K]^T + bias.  CTA tile 256x128x32, 16 warps (4x4),
// warp tile 64x32, 512 threads, 1 CTA/SM.
// 8-stage cp.async ring, mbarrier full/empty (noinc cp-arrive), no
// __syncthreads in the main loop.  Unpadded 64B rows, chunk XOR swizzle.
// MODE 0: fp32 out.  MODE 1: relu + fp16 out.
constexpr int NST    = 8;
constexpr int ROWB   = 64;                   // bytes per row (32 fp16)
constexpr int A_T    = 256 * ROWB;           // 16384 B
constexpr int B_T    = 128 * ROWB;           // 8192 B
constexpr int STAGE  = A_T + B_T;            // 24576 B
constexpr int SMEM_MAIN  = NST * STAGE;      // 196608 B
constexpr int SMEM_BYTES = SMEM_MAIN + 128;

template <int MODE>
__global__ __launch_bounds__(512, 1) void hmma_gemm(
    const __half* __restrict__ A, const __half* __restrict__ B,
    const float* __restrict__ bias, int K, int ldc,
    float* __restrict__ Cf, __half* __restrict__ Ch)
{
    extern __shared__ __align__(128) char smem[];
    const uint32_t sb = smem_u32(smem);
    const int tid = threadIdx.x;
    const int w = tid >> 5, lane = tid & 31;
    const int wm = w >> 2, wn = w & 3;        // 4x4 warp grid
    const int gid = lane >> 2, tig = lane & 3;
    const int m0 = blockIdx.y * 256, n0 = blockIdx.x * 128;
    const uint32_t mb_full  = sb + SMEM_MAIN;        // 8 x 8B
    const uint32_t mb_empty = sb + SMEM_MAIN + 64;   // 8 x 8B

    if (tid < NST) {
        MBAR_INIT(mb_full  + tid * 8, 512);
        MBAR_INIT(mb_empty + tid * 8, 16);
    }
    __syncthreads();

    float acc[4][4][4];
#pragma unroll
    for (int i = 0; i < 4; i++)
#pragma unroll
        for (int j = 0; j < 4; j++)
#pragma unroll
            for (int t = 0; t < 4; t++) acc[i][j][t] = 0.f;

    auto load_stage = [&](int s, int c) {
        const uint32_t st = sb + s * STAGE;
        const int k0 = c * 32;
        // A: 256 rows x 4 chunks = 1024 cp16, 2 per thread
#pragma unroll
        for (int t = 0; t < 2; t++) {
            int idx = tid + t * 512;
            int row = idx >> 2, ch = idx & 3;
            int chp = ch ^ ((row >> 1) & 3);
            cp16(st + row * ROWB + chp * 16,
                 A + (size_t)(m0 + row) * K + k0 + ch * 8);
        }
        // B: 128 rows x 4 chunks = 512 cp16, 1 per thread
        {
            int row = tid >> 2, ch = tid & 3;
            int chp = ch ^ ((row >> 1) & 3);
            cp16(st + A_T + row * ROWB + chp * 16,
                 B + (size_t)(n0 + row) * K + k0 + ch * 8);
        }
        asm volatile("cp.async.mbarrier.arrive.noinc.shared::cta.b64 [%0];"
                     :: "r"(mb_full + s * 8) : "memory");
    };

    const uint32_t lsel = (lane & 15), hsel = (lane >> 4);
    const uint32_t xr = (lsel >> 1) & 3;

    auto compute_stage = [&](int s) {
        const uint32_t st = sb + s * STAGE;
#pragma unroll
        for (int ks = 0; ks < 2; ks++) {
            uint32_t chp = ((uint32_t)(ks * 2) + hsel) ^ xr;
            uint32_t a_off = st + (wm * 64 + lsel) * ROWB + chp * 16;
            uint32_t b_off = st + A_T + (wn * 32 + lsel) * ROWB + chp * 16;
            uint32_t bh[2][4];
#pragma unroll
            for (int p = 0; p < 2; p++) ldmx4(bh[p], b_off + p * 16 * ROWB);
#pragma unroll
            for (int i = 0; i < 4; i++) {
                uint32_t ah[4];
                ldmx4(ah, a_off + i * 16 * ROWB);
#pragma unroll
                for (int j = 0; j < 4; j++) {
                    const int p = j >> 1, r = j & 1;
                    mma16816(acc[i][j], ah, bh[p][r], bh[p][r + 2]);
                }
            }
        }
    };

    const int C = K >> 5;
#pragma unroll
    for (int s = 0; s < NST - 1 && s < 32; s++)
        if (s < C) load_stage(s, s);
    for (int c = 0; c < C; c++) {
        const int s = c & 7;
        mbar_wait(mb_full + s * 8, (c >> 3) & 1);
        compute_stage(s);
        if (lane == 0)
            asm volatile("mbarrier.arrive.release.cta.shared::cta.b64 _, [%0];"
                         :: "r"(mb_empty + s * 8) : "memory");
        const int cn = c + NST - 1;
        if (cn < C) {
            const int sn = cn & 7, k = cn >> 3;
            if (k >= 1) mbar_wait(mb_empty + sn * 8, (k - 1) & 1);
            load_stage(sn, cn);
        }
    }

    // epilogue
    const int mr = m0 + wm * 64;
    const int nc = n0 + wn * 32;
#pragma unroll
    for (int i = 0; i < 4; i++) {
#pragma unroll
        for (int j = 0; j < 4; j++) {
            int n = nc + j * 8 + tig * 2;
            float2 bv = *(const float2*)(bias + n);
            int r_lo = mr + i * 16 + gid;
            int r_hi = r_lo + 8;
            float v00 = acc[i][j][0] + bv.x, v01 = acc[i][j][1] + bv.y;
            float v10 = acc[i][j][2] + bv.x, v11 = acc[i][j][3] + bv.y;
            if (MODE == 1) {
                v00 = fmaxf(v00, 0.f); v01 = fmaxf(v01, 0.f);
                v10 = fmaxf(v10, 0.f); v11 = fmaxf(v11, 0.f);
                *(__half2*)(Ch + (size_t)r_lo * ldc + n) =
                    __halves2half2(__float2half(v00), __float2half(v01));
                *(__half2*)(Ch + (size_t)r_hi * ldc + n) =
                    __halves2half2(__float2half(v10), __float2half(v11));
            } else {
                *(float2*)(Cf + (size_t)r_lo * ldc + n) = make_float2(v00, v01);
                *(float2*)(Cf + (size_t)r_hi * ldc + n) = make_float2(v10, v11);
            }
        }
    }
}

// ---------------- convex fixed-point + gather (warp per row) ----------------
__global__ __launch_bounds__(256) void convex_gather(
    const float* __restrict__ p, const float* __restrict__ x, float* __restrict__ out) {
    const unsigned FULL = 0xffffffffu;
    int warp = (blockIdx.x * blockDim.x + threadIdx.x) >> 5;
    int lane = threadIdx.x & 31;
    if (warp >= BB) return;

    const float* row = p + (size_t)warp * NF;
    float e[8];
    {
        float4 v0 = *(const float4*)(row + lane * 8);
        float4 v1 = *(const float4*)(row + lane * 8 + 4);
        e[0] = v0.x; e[1] = v0.y; e[2] = v0.z; e[3] = v0.w;
        e[4] = v1.x; e[5] = v1.y; e[6] = v1.z; e[7] = v1.w;
    }
#pragma unroll 2
    for (int it = 0; it < 100; ++it) {
        float lin = __shfl_up_sync(FULL, e[7], 1);
        float rin = __shfl_down_sync(FULL, e[0], 1);
        float n0 = fminf(e[0], 0.5f * (lin + e[1]));
        float n1 = fminf(e[1], 0.5f * (e[0] + e[2]));
        float n2 = fminf(e[2], 0.5f * (e[1] + e[3]));
        float n3 = fminf(e[3], 0.5f * (e[2] + e[4]));
        float n4 = fminf(e[4], 0.5f * (e[3] + e[5]));
        float n5 = fminf(e[5], 0.5f * (e[4] + e[6]));
        float n6 = fminf(e[6], 0.5f * (e[5] + e[7]));
        float n7 = fminf(e[7], 0.5f * (e[6] + rin));
        if (lane == 0)  n0 = e[0];
        if (lane == 31) n7 = e[7];
        e[0] = n0; e[1] = n1; e[2] = n2; e[3] = n3;
        e[4] = n4; e[5] = n5; e[6] = n6; e[7] = n7;
    }
    float q = x[(size_t)warp * 257 + 256];
    int idx = (int)rintf(q * 255.0f);
    idx = min(max(idx, 0), 255);
    int src_lane = idx >> 3, sub = idx & 7;
    float val = 0.f;
#pragma unroll
    for (int j = 0; j < 8; j++) {
        float t = __shfl_sync(FULL, e[j], src_lane);
        if (j == sub) val = t;
    }
    if (lane == 0) out[warp] = val;
}

// ---------------- launch ----------------
extern "C" void kernel_launch(void* const* d_in, const int* in_sizes, int n_in,
                              void* d_out, int out_size) {
    const float* x  = (const float*)d_in[0];
    const float* W1 = (const float*)d_in[1];
    const float* b1 = (const float*)d_in[2];
    const float* W2 = (const float*)d_in[3];
    const float* b2 = (const float*)d_in[4];
    float* out = (float*)d_out;

    void *pa, *pw1, *pw2, *ph, *pp;
    cudaGetSymbolAddress(&pa, g_a);
    cudaGetSymbolAddress(&pw1, g_w1);
    cudaGetSymbolAddress(&pw2, g_w2);
    cudaGetSymbolAddress(&ph, g_h);
    cudaGetSymbolAddress(&pp, g_p);

    __half* a  = (__half*)pa;
    __half* w1 = (__half*)pw1;
    __half* w2 = (__half*)pw2;
    __half* h  = (__half*)ph;
    float* prm = (float*)pp;

    cudaFuncSetAttribute(hmma_gemm<0>, cudaFuncAttributeMaxDynamicSharedMemorySize, SMEM_BYTES);
    cudaFuncSetAttribute(hmma_gemm<1>, cudaFuncAttributeMaxDynamicSharedMemorySize, SMEM_BYTES);

    conv_x<<<BB * NI / 256, 256>>>(x, a);
    conv_w<<<NH * NI / 256, 256>>>(W1, w1, NH * NI);
    conv_w<<<NF * NH / 256, 256>>>(W2, w2, NF * NH);

    // GEMM1: h = relu(x @ W1^T + b1) -> fp16
    hmma_gemm<1><<<dim3(NH / 128, BB / 256), 512, SMEM_BYTES>>>(
        a, w1, b1, NI, NH, nullptr, h);
    // GEMM2: prm = h @ W2^T + b2 (fp32)
    hmma_gemm<0><<<dim3(NF / 128, BB / 256), 512, SMEM_BYTES>>>(
        h, w2, b2, NH, NF, prm, nullptr);

    convex_gather<<<BB / 8, 256>>>(prm, x, out);
}

// round 14
// speedup vs baseline: 2.2059x; 1.0785x over previous
#include <cuda_runtime.h>
#include <cuda_fp16.h>
#include <cstdint>

#define BB 32768
#define NI 256
#define NH 1024
#define NF 256

// ---------------- scratch (device globals; no allocs allowed) ----------------
__device__ __align__(16) __half g_a[(size_t)BB * NI];    // x as fp16
__device__ __align__(16) __half g_w1[NH * NI];           // W1 as fp16
__device__ __align__(16) __half g_w2[NF * NH];           // W2 as fp16
__device__ __align__(16) __half g_h[(size_t)BB * NH];    // hidden as fp16
__device__ __align__(16) float  g_p[(size_t)BB * NF];    // param fp32

__device__ __forceinline__ uint32_t smem_u32(const void* p) {
    uint32_t a;
    asm("{ .reg .u64 t; cvta.to.shared.u64 t, %1; cvt.u32.u64 %0, t; }" : "=r"(a) : "l"(p));
    return a;
}
__device__ __forceinline__ void cp16(uint32_t saddr, const void* gaddr) {
    asm volatile("cp.async.cg.shared.global [%0], [%1], 16;\n" :: "r"(saddr), "l"(gaddr));
}
__device__ __forceinline__ void ldmx4(uint32_t* r, uint32_t addr) {
    asm volatile("ldmatrix.sync.aligned.m8n8.x4.shared.b16 {%0,%1,%2,%3}, [%4];"
                 : "=r"(r[0]), "=r"(r[1]), "=r"(r[2]), "=r"(r[3]) : "r"(addr));
}
__device__ __forceinline__ void mma16816(float* d, const uint32_t* a, uint32_t b0, uint32_t b1) {
    asm volatile(
        "mma.sync.aligned.m16n8k16.row.col.f32.f16.f16.f32 "
        "{%0,%1,%2,%3}, {%4,%5,%6,%7}, {%8,%9}, {%0,%1,%2,%3};"
        : "+f"(d[0]), "+f"(d[1]), "+f"(d[2]), "+f"(d[3])
        : "r"(a[0]), "r"(a[1]), "r"(a[2]), "r"(a[3]), "r"(b0), "r"(b1));
}
#define MBAR_INIT(mb, n)  asm volatile("mbarrier.init.shared.b64 [%0], %1;" :: "r"(mb), "r"(n) : "memory")
__device__ __forceinline__ void mbar_wait(uint32_t mb, uint32_t parity) {
    uint32_t done;
    asm volatile(
        "{\n\t.reg .pred p;\n\t"
        "mbarrier.try_wait.parity.acquire.cta.shared::cta.b64 p, [%1], %2;\n\t"
        "selp.b32 %0, 1, 0, p;\n\t}"
        : "=r"(done) : "r"(mb), "r"(parity) : "memory");
    if (!done) {
        asm volatile(
            "{\n\t.reg .pred P1;\n\t"
            "WL_%=:\n\t"
            "mbarrier.try_wait.parity.acquire.cta.shared::cta.b64 P1, [%0], %1, 0x989680;\n\t"
            "@P1 bra.uni WD_%=;\n\t"
            "bra.uni WL_%=;\n\t"
            "WD_%=:\n\t}"
            :: "r"(mb), "r"(parity) : "memory");
    }
}

// ---------------- f32x2 packed helpers (Blackwell FFMA2 path) ----------------
__device__ __forceinline__ uint64_t pack2(float lo, float hi) {
    uint64_t r;
    asm("mov.b64 %0, {%1, %2};" : "=l"(r) : "f"(lo), "f"(hi));
    return r;
}
__device__ __forceinline__ void unpack2(uint64_t v, float& lo, float& hi) {
    asm("mov.b64 {%0, %1}, %2;" : "=f"(lo), "=f"(hi) : "l"(v));
}
__device__ __forceinline__ uint64_t add2(uint64_t a, uint64_t b) {
    uint64_t r;
    asm("add.rn.f32x2 %0, %1, %2;" : "=l"(r) : "l"(a), "l"(b));
    return r;
}
__device__ __forceinline__ uint64_t mul2(uint64_t a, uint64_t b) {
    uint64_t r;
    asm("mul.rn.f32x2 %0, %1, %2;" : "=l"(r) : "l"(a), "l"(b));
    return r;
}
__device__ __forceinline__ uint64_t min2(uint64_t a, uint64_t b) {
    float ax, ay, bx, by;
    unpack2(a, ax, ay); unpack2(b, bx, by);
    return pack2(fminf(ax, bx), fminf(ay, by));
}

// ---------------- fp16 convert kernels ----------------
__global__ __launch_bounds__(256) void conv_x(const float* __restrict__ x,
                                              __half* __restrict__ o) {
    int i = blockIdx.x * 256 + threadIdx.x;           // i < BB*NI
    int r = i >> 8, c = i & 255;
    o[i] = __float2half(x[(size_t)r * 257 + c]);
}
__global__ __launch_bounds__(256) void conv_w(const float* __restrict__ w,
                                              __half* __restrict__ o, int n) {
    int i = blockIdx.x * 256 + threadIdx.x;
    if (i < n) o[i] = __float2half(w[i]);
}

// ---------------- HMMA GEMM (mma.sync m16n8k16 fp16, single pass) ----------
// C[M,N] = A[M,K] @ B[N,K]^T + bias.  CTA tile 256x128x32, 16 warps (4x4),
// warp tile 64x32, 512 threads, 1 CTA/SM.
// 8-stage cp.async ring, mbarrier full/empty (noinc cp-arrive), no
// __syncthreads in the main loop.  Unpadded 64B rows, chunk XOR swizzle.
// MODE 0: fp32 out.  MODE 1: relu + fp16 out.
constexpr int NST    = 8;
constexpr int ROWB   = 64;                   // bytes per row (32 fp16)
constexpr int A_T    = 256 * ROWB;           // 16384 B
constexpr int B_T    = 128 * ROWB;           // 8192 B
constexpr int STAGE  = A_T + B_T;            // 24576 B
constexpr int SMEM_MAIN  = NST * STAGE;      // 196608 B
constexpr int SMEM_BYTES = SMEM_MAIN + 128;

template <int MODE>
__global__ __launch_bounds__(512, 1) void hmma_gemm(
    const __half* __restrict__ A, const __half* __restrict__ B,
    const float* __restrict__ bias, int K, int ldc,
    float* __restrict__ Cf, __half* __restrict__ Ch)
{
    extern __shared__ __align__(128) char smem[];
    const uint32_t sb = smem_u32(smem);
    const int tid = threadIdx.x;
    const int w = tid >> 5, lane = tid & 31;
    const int wm = w >> 2, wn = w & 3;        // 4x4 warp grid
    const int gid = lane >> 2, tig = lane & 3;
    const int m0 = blockIdx.y * 256, n0 = blockIdx.x * 128;
    const uint32_t mb_full  = sb + SMEM_MAIN;        // 8 x 8B
    const uint32_t mb_empty = sb + SMEM_MAIN + 64;   // 8 x 8B

    if (tid < NST) {
        MBAR_INIT(mb_full  + tid * 8, 512);
        MBAR_INIT(mb_empty + tid * 8, 16);
    }
    __syncthreads();

    float acc[4][4][4];
#pragma unroll
    for (int i = 0; i < 4; i++)
#pragma unroll
        for (int j = 0; j < 4; j++)
#pragma unroll
            for (int t = 0; t < 4; t++) acc[i][j][t] = 0.f;

    auto load_stage = [&](int s, int c) {
        const uint32_t st = sb + s * STAGE;
        const int k0 = c * 32;
#pragma unroll
        for (int t = 0; t < 2; t++) {
            int idx = tid + t * 512;
            int row = idx >> 2, ch = idx & 3;
            int chp = ch ^ ((row >> 1) & 3);
            cp16(st + row * ROWB + chp * 16,
                 A + (size_t)(m0 + row) * K + k0 + ch * 8);
        }
        {
            int row = tid >> 2, ch = tid & 3;
            int chp = ch ^ ((row >> 1) & 3);
            cp16(st + A_T + row * ROWB + chp * 16,
                 B + (size_t)(n0 + row) * K + k0 + ch * 8);
        }
        asm volatile("cp.async.mbarrier.arrive.noinc.shared::cta.b64 [%0];"
                     :: "r"(mb_full + s * 8) : "memory");
    };

    const uint32_t lsel = (lane & 15), hsel = (lane >> 4);
    const uint32_t xr = (lsel >> 1) & 3;

    auto compute_stage = [&](int s) {
        const uint32_t st = sb + s * STAGE;
#pragma unroll
        for (int ks = 0; ks < 2; ks++) {
            uint32_t chp = ((uint32_t)(ks * 2) + hsel) ^ xr;
            uint32_t a_off = st + (wm * 64 + lsel) * ROWB + chp * 16;
            uint32_t b_off = st + A_T + (wn * 32 + lsel) * ROWB + chp * 16;
            uint32_t bh[2][4];
#pragma unroll
            for (int p = 0; p < 2; p++) ldmx4(bh[p], b_off + p * 16 * ROWB);
#pragma unroll
            for (int i = 0; i < 4; i++) {
                uint32_t ah[4];
                ldmx4(ah, a_off + i * 16 * ROWB);
#pragma unroll
                for (int j = 0; j < 4; j++) {
                    const int p = j >> 1, r = j & 1;
                    mma16816(acc[i][j], ah, bh[p][r], bh[p][r + 2]);
                }
            }
        }
    };

    const int C = K >> 5;
#pragma unroll
    for (int s = 0; s < NST - 1 && s < 32; s++)
        if (s < C) load_stage(s, s);
    for (int c = 0; c < C; c++) {
        const int s = c & 7;
        mbar_wait(mb_full + s * 8, (c >> 3) & 1);
        compute_stage(s);
        if (lane == 0)
            asm volatile("mbarrier.arrive.release.cta.shared::cta.b64 _, [%0];"
                         :: "r"(mb_empty + s * 8) : "memory");
        const int cn = c + NST - 1;
        if (cn < C) {
            const int sn = cn & 7, k = cn >> 3;
            if (k >= 1) mbar_wait(mb_empty + sn * 8, (k - 1) & 1);
            load_stage(sn, cn);
        }
    }

    // epilogue
    const int mr = m0 + wm * 64;
    const int nc = n0 + wn * 32;
#pragma unroll
    for (int i = 0; i < 4; i++) {
#pragma unroll
        for (int j = 0; j < 4; j++) {
            int n = nc + j * 8 + tig * 2;
            float2 bv = *(const float2*)(bias + n);
            int r_lo = mr + i * 16 + gid;
            int r_hi = r_lo + 8;
            float v00 = acc[i][j][0] + bv.x, v01 = acc[i][j][1] + bv.y;
            float v10 = acc[i][j][2] + bv.x, v11 = acc[i][j][3] + bv.y;
            if (MODE == 1) {
                v00 = fmaxf(v00, 0.f); v01 = fmaxf(v01, 0.f);
                v10 = fmaxf(v10, 0.f); v11 = fmaxf(v11, 0.f);
                *(__half2*)(Ch + (size_t)r_lo * ldc + n) =
                    __halves2half2(__float2half(v00), __float2half(v01));
                *(__half2*)(Ch + (size_t)r_hi * ldc + n) =
                    __halves2half2(__float2half(v10), __float2half(v11));
            } else {
                *(float2*)(Cf + (size_t)r_lo * ldc + n) = make_float2(v00, v01);
                *(float2*)(Cf + (size_t)r_hi * ldc + n) = make_float2(v10, v11);
            }
        }
    }
}

// ---------------- convex fixed-point + gather: 2 rows/warp, f32x2 SIMD ------
// Lane l holds elements [8l,8l+7] of rows (2w) and (2w+1) packed as f32x2.
// Per iteration: 8 add.f32x2 + 8 mul.f32x2 (fma pipe) + 16 scalar fmin (alu),
// i.e. half the fma-pipe work per row of the scalar version. IEEE-rn packed
// math == scalar math bit-for-bit.
__global__ __launch_bounds__(256) void convex_gather2(
    const float* __restrict__ p, const float* __restrict__ x, float* __restrict__ out) {
    const unsigned FULL = 0xffffffffu;
    int warp = (blockIdx.x * blockDim.x + threadIdx.x) >> 5;   // < BB/2
    int lane = threadIdx.x & 31;
    int rowA = warp * 2, rowB = warp * 2 + 1;

    const float* pa = p + (size_t)rowA * NF + lane * 8;
    const float* pb = p + (size_t)rowB * NF + lane * 8;
    uint64_t e[8];
    {
        float4 a0 = *(const float4*)(pa);
        float4 a1 = *(const float4*)(pa + 4);
        float4 b0 = *(const float4*)(pb);
        float4 b1 = *(const float4*)(pb + 4);
        e[0] = pack2(a0.x, b0.x); e[1] = pack2(a0.y, b0.y);
        e[2] = pack2(a0.z, b0.z); e[3] = pack2(a0.w, b0.w);
        e[4] = pack2(a1.x, b1.x); e[5] = pack2(a1.y, b1.y);
        e[6] = pack2(a1.z, b1.z); e[7] = pack2(a1.w, b1.w);
    }
    const uint64_t HALF2 = pack2(0.5f, 0.5f);

#pragma unroll 2
    for (int it = 0; it < 100; ++it) {
        uint64_t lin = __shfl_up_sync(FULL, e[7], 1);
        uint64_t rin = __shfl_down_sync(FULL, e[0], 1);
        uint64_t n0 = min2(e[0], mul2(add2(lin,  e[1]), HALF2));
        uint64_t n1 = min2(e[1], mul2(add2(e[0], e[2]), HALF2));
        uint64_t n2 = min2(e[2], mul2(add2(e[1], e[3]), HALF2));
        uint64_t n3 = min2(e[3], mul2(add2(e[2], e[4]), HALF2));
        uint64_t n4 = min2(e[4], mul2(add2(e[3], e[5]), HALF2));
        uint64_t n5 = min2(e[5], mul2(add2(e[4], e[6]), HALF2));
        uint64_t n6 = min2(e[6], mul2(add2(e[5], e[7]), HALF2));
        uint64_t n7 = min2(e[7], mul2(add2(e[6], rin ), HALF2));
        if (lane == 0)  n0 = e[0];   // global index 0 fixed
        if (lane == 31) n7 = e[7];   // global index 255 fixed
        e[0] = n0; e[1] = n1; e[2] = n2; e[3] = n3;
        e[4] = n4; e[5] = n5; e[6] = n6; e[7] = n7;
    }

    // gather per row: idx = round-half-even(q * 255)
    float qa = x[(size_t)rowA * 257 + 256];
    float qb = x[(size_t)rowB * 257 + 256];
    int idxA = min(max((int)rintf(qa * 255.0f), 0), 255);
    int idxB = min(max((int)rintf(qb * 255.0f), 0), 255);
    int slA = idxA >> 3, sbA = idxA & 7;
    int slB = idxB >> 3, sbB = idxB & 7;
    float valA = 0.f, valB = 0.f;
#pragma unroll
    for (int j = 0; j < 8; j++) {
        uint64_t ta = __shfl_sync(FULL, e[j], slA);
        uint64_t tb = __shfl_sync(FULL, e[j], slB);
        float tax, tay, tbx, tby;
        unpack2(ta, tax, tay);
        unpack2(tb, tbx, tby);
        if (j == sbA) valA = tax;
        if (j == sbB) valB = tby;
    }
    if (lane == 0) {
        out[rowA] = valA;
        out[rowB] = valB;
    }
}

// ---------------- launch ----------------
extern "C" void kernel_launch(void* const* d_in, const int* in_sizes, int n_in,
                              void* d_out, int out_size) {
    const float* x  = (const float*)d_in[0];
    const float* W1 = (const float*)d_in[1];
    const float* b1 = (const float*)d_in[2];
    const float* W2 = (const float*)d_in[3];
    const float* b2 = (const float*)d_in[4];
    float* out = (float*)d_out;

    void *pa, *pw1, *pw2, *ph, *pp;
    cudaGetSymbolAddress(&pa, g_a);
    cudaGetSymbolAddress(&pw1, g_w1);
    cudaGetSymbolAddress(&pw2, g_w2);
    cudaGetSymbolAddress(&ph, g_h);
    cudaGetSymbolAddress(&pp, g_p);

    __half* a  = (__half*)pa;
    __half* w1 = (__half*)pw1;
    __half* w2 = (__half*)pw2;
    __half* h  = (__half*)ph;
    float* prm = (float*)pp;

    cudaFuncSetAttribute(hmma_gemm<0>, cudaFuncAttributeMaxDynamicSharedMemorySize, SMEM_BYTES);
    cudaFuncSetAttribute(hmma_gemm<1>, cudaFuncAttributeMaxDynamicSharedMemorySize, SMEM_BYTES);

    conv_x<<<BB * NI / 256, 256>>>(x, a);
    conv_w<<<NH * NI / 256, 256>>>(W1, w1, NH * NI);
    conv_w<<<NF * NH / 256, 256>>>(W2, w2, NF * NH);

    // GEMM1: h = relu(x @ W1^T + b1) -> fp16
    hmma_gemm<1><<<dim3(NH / 128, BB / 256), 512, SMEM_BYTES>>>(
        a, w1, b1, NI, NH, nullptr, h);
    // GEMM2: prm = h @ W2^T + b2 (fp32)
    hmma_gemm<0><<<dim3(NF / 128, BB / 256), 512, SMEM_BYTES>>>(
        h, w2, b2, NH, NF, prm, nullptr);

    // convex solver: 2 rows per warp, f32x2 packed
    convex_gather2<<<BB / 16, 256>>>(prm, x, out);
}

// round 16
// speedup vs baseline: 2.3455x; 1.0633x over previous
#include <cuda_runtime.h>
#include <cuda_fp16.h>
#include <cstdint>

#define BB 32768
#define NI 256
#define NH 1024
#define NF 256

// ---------------- scratch (device globals; no allocs allowed) ----------------
// All GEMM operands stored as pre-swizzled tile images:
//   A-style: [mblk(256 rows)][kchunk(32)][row 0..255][64B row, chunk-XOR swizzled]
//   B-style: [nblk(128 rows)][kchunk(32)][row 0..127][64B row, chunk-XOR swizzled]
// so each (blk, kchunk) stage is one CONTIGUOUS 16384B / 8192B span -> 1 bulk copy.
__device__ __align__(256) __half g_a[(size_t)BB * NI];    // x image (A of GEMM1)
__device__ __align__(256) __half g_w1[NH * NI];           // W1 image (B of GEMM1)
__device__ __align__(256) __half g_w2[NF * NH];           // W2 image (B of GEMM2)
__device__ __align__(256) __half g_h[(size_t)BB * NH];    // hidden image (A of GEMM2)
__device__ __align__(256) float  g_p[(size_t)BB * NF];    // param fp32 (plain row-major)

__device__ __forceinline__ uint32_t smem_u32(const void* p) {
    uint32_t a;
    asm("{ .reg .u64 t; cvta.to.shared.u64 t, %1; cvt.u32.u64 %0, t; }" : "=r"(a) : "l"(p));
    return a;
}
__device__ __forceinline__ void bulk_cp(uint32_t dst, const void* src, uint32_t bytes, uint32_t mbar) {
    asm volatile(
        "cp.async.bulk.shared::cluster.global.mbarrier::complete_tx::bytes [%0], [%1], %2, [%3];"
        :: "r"(dst), "l"(src), "r"(bytes), "r"(mbar) : "memory");
}
__device__ __forceinline__ void ldmx4(uint32_t* r, uint32_t addr) {
    asm volatile("ldmatrix.sync.aligned.m8n8.x4.shared.b16 {%0,%1,%2,%3}, [%4];"
                 : "=r"(r[0]), "=r"(r[1]), "=r"(r[2]), "=r"(r[3]) : "r"(addr));
}
__device__ __forceinline__ void mma16816(float* d, const uint32_t* a, uint32_t b0, uint32_t b1) {
    asm volatile(
        "mma.sync.aligned.m16n8k16.row.col.f32.f16.f16.f32 "
        "{%0,%1,%2,%3}, {%4,%5,%6,%7}, {%8,%9}, {%0,%1,%2,%3};"
        : "+f"(d[0]), "+f"(d[1]), "+f"(d[2]), "+f"(d[3])
        : "r"(a[0]), "r"(a[1]), "r"(a[2]), "r"(a[3]), "r"(b0), "r"(b1));
}
#define MBAR_INIT(mb, n)  asm volatile("mbarrier.init.shared.b64 [%0], %1;" :: "r"(mb), "r"(n) : "memory")
#define MBAR_EXPECT_TX(mb, bytes) \
    asm volatile("mbarrier.arrive.expect_tx.shared.b64 _, [%0], %1;" :: "r"(mb), "r"(bytes) : "memory")
__device__ __forceinline__ void mbar_wait(uint32_t mb, uint32_t parity) {
    uint32_t done;
    asm volatile(
        "{\n\t.reg .pred p;\n\t"
        "mbarrier.try_wait.parity.acquire.cta.shared::cta.b64 p, [%1], %2;\n\t"
        "selp.b32 %0, 1, 0, p;\n\t}"
        : "=r"(done) : "r"(mb), "r"(parity) : "memory");
    if (!done) {
        asm volatile(
            "{\n\t.reg .pred P1;\n\t"
            "WL_%=:\n\t"
            "mbarrier.try_wait.parity.acquire.cta.shared::cta.b64 P1, [%0], %1, 0x989680;\n\t"
            "@P1 bra.uni WD_%=;\n\t"
            "bra.uni WL_%=;\n\t"
            "WD_%=:\n\t}"
            :: "r"(mb), "r"(parity) : "memory");
    }
}

// ---------------- f32x2 packed helpers ----------------
__device__ __forceinline__ uint64_t pack2(float lo, float hi) {
    uint64_t r;
    asm("mov.b64 %0, {%1, %2};" : "=l"(r) : "f"(lo), "f"(hi));
    return r;
}
__device__ __forceinline__ void unpack2(uint64_t v, float& lo, float& hi) {
    asm("mov.b64 {%0, %1}, %2;" : "=f"(lo), "=f"(hi) : "l"(v));
}
__device__ __forceinline__ uint64_t add2(uint64_t a, uint64_t b) {
    uint64_t r;
    asm("add.rn.f32x2 %0, %1, %2;" : "=l"(r) : "l"(a), "l"(b));
    return r;
}
__device__ __forceinline__ uint64_t mul2(uint64_t a, uint64_t b) {
    uint64_t r;
    asm("mul.rn.f32x2 %0, %1, %2;" : "=l"(r) : "l"(a), "l"(b));
    return r;
}
__device__ __forceinline__ uint64_t min2(uint64_t a, uint64_t b) {
    float ax, ay, bx, by;
    unpack2(a, ax, ay); unpack2(b, bx, by);
    return pack2(fminf(ax, bx), fminf(ay, by));
}

// ---------------- converters: fp32 -> fp16 tile images ----------------
__global__ __launch_bounds__(256) void conv_x(const float* __restrict__ x,
                                              __half* __restrict__ o) {
    int i = blockIdx.x * 256 + threadIdx.x;           // i < BB*NI
    int r = i >> 8, c = i & 255;
    int row = r & 255;
    int ch = (c & 31) >> 3;
    int chp = ch ^ ((row >> 1) & 3);
    size_t off = ((size_t)(r >> 8) * 8 + (c >> 5)) * 8192 + row * 32 + chp * 8 + (c & 7);
    o[off] = __float2half(x[(size_t)r * 257 + c]);
}
// B-style image (128-row blocks).  kbits = log2(K), C = K/32.
__global__ __launch_bounds__(256) void conv_w(const float* __restrict__ w,
                                              __half* __restrict__ o, int n,
                                              int kbits, int C) {
    int i = blockIdx.x * 256 + threadIdx.x;
    if (i >= n) return;
    int r = i >> kbits, c = i & ((1 << kbits) - 1);
    int row = r & 127;
    int ch = (c & 31) >> 3;
    int chp = ch ^ ((row >> 1) & 3);
    size_t off = ((size_t)(r >> 7) * C + (c >> 5)) * 4096 + row * 32 + chp * 8 + (c & 7);
    o[off] = __float2half(w[i]);
}

// ---------------- bulk-TMA HMMA GEMM (mma.sync m16n8k16 fp16) ---------------
// C[M,N] = A[M,K] @ B[N,K]^T + bias.  CTA tile 256x128x32, 16 warps (4x4),
// warp tile 64x32, 512 threads, 1 CTA/SM.
// 8-stage ring; thread 0 issues ONE cp.async.bulk per operand per stage
// (sources are pre-swizzled contiguous tile images) + expect_tx; all threads
// wait the full barrier; 16 warps arrive the empty barrier.  No per-16B
// LDGSTS anywhere - the former bottleneck.
// MODE 0: fp32 out (plain).  MODE 1: relu + fp16 out in A-style image (K=1024).
constexpr int NST    = 8;
constexpr int ROWB   = 64;
constexpr int A_T    = 256 * ROWB;           // 16384 B
constexpr int B_T    = 128 * ROWB;           // 8192 B
constexpr int STAGE  = A_T + B_T;            // 24576 B
constexpr int SMEM_MAIN  = NST * STAGE;      // 196608 B
constexpr int SMEM_BYTES = SMEM_MAIN + 128;

template <int MODE>
__global__ __launch_bounds__(512, 1) void hmma_gemm(
    const __half* __restrict__ A, const __half* __restrict__ B,
    const float* __restrict__ bias, int K, int ldc,
    float* __restrict__ Cf, __half* __restrict__ Ch)
{
    extern __shared__ __align__(128) char smem[];
    const uint32_t sb = smem_u32(smem);
    const int tid = threadIdx.x;
    const int w = tid >> 5, lane = tid & 31;
    const int wm = w >> 2, wn = w & 3;        // 4x4 warp grid
    const int gid = lane >> 2, tig = lane & 3;
    const int m0 = blockIdx.y * 256, n0 = blockIdx.x * 128;
    const uint32_t mb_full  = sb + SMEM_MAIN;
    const uint32_t mb_empty = sb + SMEM_MAIN + 64;
    const int C = K >> 5;

    if (tid < NST) {
        MBAR_INIT(mb_full  + tid * 8, 1);     // expect_tx arrive from thread 0
        MBAR_INIT(mb_empty + tid * 8, 16);    // one arrive per warp
    }
    __syncthreads();

    float acc[4][4][4];
#pragma unroll
    for (int i = 0; i < 4; i++)
#pragma unroll
        for (int j = 0; j < 4; j++)
#pragma unroll
            for (int t = 0; t < 4; t++) acc[i][j][t] = 0.f;

    auto issue_stage = [&](int s, int c) {    // thread 0 only
        const uint32_t st = sb + s * STAGE;
        MBAR_EXPECT_TX(mb_full + s * 8, (uint32_t)STAGE);
        bulk_cp(st,       A + ((size_t)blockIdx.y * C + c) * 8192, A_T, mb_full + s * 8);
        bulk_cp(st + A_T, B + ((size_t)blockIdx.x * C + c) * 4096, B_T, mb_full + s * 8);
    };

    const uint32_t lsel = (lane & 15), hsel = (lane >> 4);
    const uint32_t xr = (lsel >> 1) & 3;

    auto compute_stage = [&](int s) {
        const uint32_t st = sb + s * STAGE;
#pragma unroll
        for (int ks = 0; ks < 2; ks++) {
            uint32_t chp = ((uint32_t)(ks * 2) + hsel) ^ xr;
            uint32_t a_off = st + (wm * 64 + lsel) * ROWB + chp * 16;
            uint32_t b_off = st + A_T + (wn * 32 + lsel) * ROWB + chp * 16;
            uint32_t bh[2][4];
#pragma unroll
            for (int p = 0; p < 2; p++) ldmx4(bh[p], b_off + p * 16 * ROWB);
#pragma unroll
            for (int i = 0; i < 4; i++) {
                uint32_t ah[4];
                ldmx4(ah, a_off + i * 16 * ROWB);
#pragma unroll
                for (int j = 0; j < 4; j++) {
                    const int p = j >> 1, r = j & 1;
                    mma16816(acc[i][j], ah, bh[p][r], bh[p][r + 2]);
                }
            }
        }
    };

    if (tid == 0) {
        for (int s = 0; s < NST - 1 && s < C; s++) issue_stage(s, s);
    }
    for (int c = 0; c < C; c++) {
        const int s = c & 7;
        mbar_wait(mb_full + s * 8, (c >> 3) & 1);
        compute_stage(s);
        if (lane == 0)
            asm volatile("mbarrier.arrive.release.cta.shared::cta.b64 _, [%0];"
                         :: "r"(mb_empty + s * 8) : "memory");
        if (tid == 0) {
            const int cn = c + NST - 1;
            if (cn < C) {
                const int sn = cn & 7, k = cn >> 3;
                if (k >= 1) mbar_wait(mb_empty + sn * 8, (k - 1) & 1);
                issue_stage(sn, cn);
            }
        }
    }

    // epilogue
    const int mr = m0 + wm * 64;
    const int nc = n0 + wn * 32;
#pragma unroll
    for (int i = 0; i < 4; i++) {
#pragma unroll
        for (int j = 0; j < 4; j++) {
            int n = nc + j * 8 + tig * 2;
            float2 bv = *(const float2*)(bias + n);
            int r_lo = mr + i * 16 + gid;
            int r_hi = r_lo + 8;
            float v00 = acc[i][j][0] + bv.x, v01 = acc[i][j][1] + bv.y;
            float v10 = acc[i][j][2] + bv.x, v11 = acc[i][j][3] + bv.y;
            if (MODE == 1) {
                v00 = fmaxf(v00, 0.f); v01 = fmaxf(v01, 0.f);
                v10 = fmaxf(v10, 0.f); v11 = fmaxf(v11, 0.f);
                // write A-style image for GEMM2 (K=1024 -> 32 kchunks/block)
                int ch = (n & 31) >> 3;
#pragma unroll
                for (int t2 = 0; t2 < 2; t2++) {
                    int r = t2 ? r_hi : r_lo;
                    int row = r & 255;
                    int chp = ch ^ ((row >> 1) & 3);
                    size_t off = ((size_t)(r >> 8) * 32 + (n >> 5)) * 8192
                               + row * 32 + chp * 8 + (n & 7);
                    *(__half2*)(Ch + off) = t2
                        ? __halves2half2(__float2half(v10), __float2half(v11))
                        : __halves2half2(__float2half(v00), __float2half(v01));
                }
            } else {
                *(float2*)(Cf + (size_t)r_lo * ldc + n) = make_float2(v00, v01);
                *(float2*)(Cf + (size_t)r_hi * ldc + n) = make_float2(v10, v11);
            }
        }
    }
}

// ---------------- convex fixed-point + gather: 2 rows/warp, f32x2 SIMD ------
__global__ __launch_bounds__(256) void convex_gather2(
    const float* __restrict__ p, const float* __restrict__ x, float* __restrict__ out) {
    const unsigned FULL = 0xffffffffu;
    int warp = (blockIdx.x * blockDim.x + threadIdx.x) >> 5;   // < BB/2
    int lane = threadIdx.x & 31;
    int rowA = warp * 2, rowB = warp * 2 + 1;

    const float* pa = p + (size_t)rowA * NF + lane * 8;
    const float* pb = p + (size_t)rowB * NF + lane * 8;
    uint64_t e[8];
    {
        float4 a0 = *(const float4*)(pa);
        float4 a1 = *(const float4*)(pa + 4);
        float4 b0 = *(const float4*)(pb);
        float4 b1 = *(const float4*)(pb + 4);
        e[0] = pack2(a0.x, b0.x); e[1] = pack2(a0.y, b0.y);
        e[2] = pack2(a0.z, b0.z); e[3] = pack2(a0.w, b0.w);
        e[4] = pack2(a1.x, b1.x); e[5] = pack2(a1.y, b1.y);
        e[6] = pack2(a1.z, b1.z); e[7] = pack2(a1.w, b1.w);
    }
    const uint64_t HALF2 = pack2(0.5f, 0.5f);

#pragma unroll 2
    for (int it = 0; it < 100; ++it) {
        uint64_t lin = __shfl_up_sync(FULL, e[7], 1);
        uint64_t rin = __shfl_down_sync(FULL, e[0], 1);
        uint64_t n0 = min2(e[0], mul2(add2(lin,  e[1]), HALF2));
        uint64_t n1 = min2(e[1], mul2(add2(e[0], e[2]), HALF2));
        uint64_t n2 = min2(e[2], mul2(add2(e[1], e[3]), HALF2));
        uint64_t n3 = min2(e[3], mul2(add2(e[2], e[4]), HALF2));
        uint64_t n4 = min2(e[4], mul2(add2(e[3], e[5]), HALF2));
        uint64_t n5 = min2(e[5], mul2(add2(e[4], e[6]), HALF2));
        uint64_t n6 = min2(e[6], mul2(add2(e[5], e[7]), HALF2));
        uint64_t n7 = min2(e[7], mul2(add2(e[6], rin ), HALF2));
        if (lane == 0)  n0 = e[0];
        if (lane == 31) n7 = e[7];
        e[0] = n0; e[1] = n1; e[2] = n2; e[3] = n3;
        e[4] = n4; e[5] = n5; e[6] = n6; e[7] = n7;
    }

    float qa = x[(size_t)rowA * 257 + 256];
    float qb = x[(size_t)rowB * 257 + 256];
    int idxA = min(max((int)rintf(qa * 255.0f), 0), 255);
    int idxB = min(max((int)rintf(qb * 255.0f), 0), 255);
    int slA = idxA >> 3, sbA = idxA & 7;
    int slB = idxB >> 3, sbB = idxB & 7;
    float valA = 0.f, valB = 0.f;
#pragma unroll
    for (int j = 0; j < 8; j++) {
        uint64_t ta = __shfl_sync(FULL, e[j], slA);
        uint64_t tb = __shfl_sync(FULL, e[j], slB);
        float tax, tay, tbx, tby;
        unpack2(ta, tax, tay);
        unpack2(tb, tbx, tby);
        if (j == sbA) valA = tax;
        if (j == sbB) valB = tby;
    }
    if (lane == 0) {
        out[rowA] = valA;
        out[rowB] = valB;
    }
}

// ---------------- launch ----------------
extern "C" void kernel_launch(void* const* d_in, const int* in_sizes, int n_in,
                              void* d_out, int out_size) {
    const float* x  = (const float*)d_in[0];
    const float* W1 = (const float*)d_in[1];
    const float* b1 = (const float*)d_in[2];
    const float* W2 = (const float*)d_in[3];
    const float* b2 = (const float*)d_in[4];
    float* out = (float*)d_out;

    void *pa, *pw1, *pw2, *ph, *pp;
    cudaGetSymbolAddress(&pa, g_a);
    cudaGetSymbolAddress(&pw1, g_w1);
    cudaGetSymbolAddress(&pw2, g_w2);
    cudaGetSymbolAddress(&ph, g_h);
    cudaGetSymbolAddress(&pp, g_p);

    __half* a  = (__half*)pa;
    __half* w1 = (__half*)pw1;
    __half* w2 = (__half*)pw2;
    __half* h  = (__half*)ph;
    float* prm = (float*)pp;

    cudaFuncSetAttribute(hmma_gemm<0>, cudaFuncAttributeMaxDynamicSharedMemorySize, SMEM_BYTES);
    cudaFuncSetAttribute(hmma_gemm<1>, cudaFuncAttributeMaxDynamicSharedMemorySize, SMEM_BYTES);

    conv_x<<<BB * NI / 256, 256>>>(x, a);
    conv_w<<<NH * NI / 256, 256>>>(W1, w1, NH * NI, 8, 8);     // K=256, C=8
    conv_w<<<NF * NH / 256, 256>>>(W2, w2, NF * NH, 10, 32);   // K=1024, C=32

    // GEMM1: h = relu(x @ W1^T + b1) -> fp16 A-image
    hmma_gemm<1><<<dim3(NH / 128, BB / 256), 512, SMEM_BYTES>>>(
        a, w1, b1, NI, NH, nullptr, h);
    // GEMM2: prm = h @ W2^T + b2 (fp32 plain)
    hmma_gemm<0><<<dim3(NF / 128, BB / 256), 512, SMEM_BYTES>>>(
        h, w2, b2, NH, NF, prm, nullptr);

    convex_gather2<<<BB / 16, 256>>>(prm, x, out);
}

// round 17
// speedup vs baseline: 2.3979x; 1.0223x over previous
#include <cuda_runtime.h>
#include <cuda_fp16.h>
#include <cstdint>

#define BB 32768
#define NI 256
#define NH 1024
#define NF 256

// ---------------- scratch (device globals; no allocs allowed) ----------------
// All GEMM operands stored as pre-swizzled 128-row tile images:
//   [blk(128 rows)][kchunk(32 halves)][row 0..127][64B row, chunk-XOR swizzled]
// -> each (blk, kchunk) span is one CONTIGUOUS 8192B bulk copy.
__device__ __align__(256) __half g_a[(size_t)BB * NI];    // x image (A of GEMM1)
__device__ __align__(256) __half g_w1[NH * NI];           // W1 image (B of GEMM1)
__device__ __align__(256) __half g_w2[NF * NH];           // W2 image (B of GEMM2)
__device__ __align__(256) __half g_h[(size_t)BB * NH];    // hidden image (A of GEMM2)
__device__ __align__(256) float  g_p[(size_t)BB * NF];    // param fp32 (plain row-major)

__device__ __forceinline__ uint32_t smem_u32(const void* p) {
    uint32_t a;
    asm("{ .reg .u64 t; cvta.to.shared.u64 t, %1; cvt.u32.u64 %0, t; }" : "=r"(a) : "l"(p));
    return a;
}
__device__ __forceinline__ void bulk_cp(uint32_t dst, const void* src, uint32_t bytes, uint32_t mbar) {
    asm volatile(
        "cp.async.bulk.shared::cluster.global.mbarrier::complete_tx::bytes [%0], [%1], %2, [%3];"
        :: "r"(dst), "l"(src), "r"(bytes), "r"(mbar) : "memory");
}
__device__ __forceinline__ void ldmx4(uint32_t* r, uint32_t addr) {
    asm volatile("ldmatrix.sync.aligned.m8n8.x4.shared.b16 {%0,%1,%2,%3}, [%4];"
                 : "=r"(r[0]), "=r"(r[1]), "=r"(r[2]), "=r"(r[3]) : "r"(addr));
}
__device__ __forceinline__ void mma16816(float* d, const uint32_t* a, uint32_t b0, uint32_t b1) {
    asm volatile(
        "mma.sync.aligned.m16n8k16.row.col.f32.f16.f16.f32 "
        "{%0,%1,%2,%3}, {%4,%5,%6,%7}, {%8,%9}, {%0,%1,%2,%3};"
        : "+f"(d[0]), "+f"(d[1]), "+f"(d[2]), "+f"(d[3])
        : "r"(a[0]), "r"(a[1]), "r"(a[2]), "r"(a[3]), "r"(b0), "r"(b1));
}
#define MBAR_INIT(mb, n)  asm volatile("mbarrier.init.shared.b64 [%0], %1;" :: "r"(mb), "r"(n) : "memory")
#define MBAR_EXPECT_TX(mb, bytes) \
    asm volatile("mbarrier.arrive.expect_tx.shared.b64 _, [%0], %1;" :: "r"(mb), "r"(bytes) : "memory")
__device__ __forceinline__ void mbar_wait(uint32_t mb, uint32_t parity) {
    uint32_t done;
    asm volatile(
        "{\n\t.reg .pred p;\n\t"
        "mbarrier.try_wait.parity.acquire.cta.shared::cta.b64 p, [%1], %2;\n\t"
        "selp.b32 %0, 1, 0, p;\n\t}"
        : "=r"(done) : "r"(mb), "r"(parity) : "memory");
    if (!done) {
        asm volatile(
            "{\n\t.reg .pred P1;\n\t"
            "WL_%=:\n\t"
            "mbarrier.try_wait.parity.acquire.cta.shared::cta.b64 P1, [%0], %1, 0x989680;\n\t"
            "@P1 bra.uni WD_%=;\n\t"
            "bra.uni WL_%=;\n\t"
            "WD_%=:\n\t}"
            :: "r"(mb), "r"(parity) : "memory");
    }
}

// ---------------- f32x2 packed helpers ----------------
__device__ __forceinline__ uint64_t pack2(float lo, float hi) {
    uint64_t r;
    asm("mov.b64 %0, {%1, %2};" : "=l"(r) : "f"(lo), "f"(hi));
    return r;
}
__device__ __forceinline__ void unpack2(uint64_t v, float& lo, float& hi) {
    asm("mov.b64 {%0, %1}, %2;" : "=f"(lo), "=f"(hi) : "l"(v));
}
__device__ __forceinline__ uint64_t add2(uint64_t a, uint64_t b) {
    uint64_t r;
    asm("add.rn.f32x2 %0, %1, %2;" : "=l"(r) : "l"(a), "l"(b));
    return r;
}
__device__ __forceinline__ uint64_t mul2(uint64_t a, uint64_t b) {
    uint64_t r;
    asm("mul.rn.f32x2 %0, %1, %2;" : "=l"(r) : "l"(a), "l"(b));
    return r;
}
__device__ __forceinline__ uint64_t min2(uint64_t a, uint64_t b) {
    float ax, ay, bx, by;
    unpack2(a, ax, ay); unpack2(b, bx, by);
    return pack2(fminf(ax, bx), fminf(ay, by));
}

// ---------------- converters: fp32 -> fp16 128-row tile images --------------
// kbits = log2(K), C = K/32.
__global__ __launch_bounds__(256) void conv_x(const float* __restrict__ x,
                                              __half* __restrict__ o) {
    int i = blockIdx.x * 256 + threadIdx.x;           // i < BB*NI
    int r = i >> 8, c = i & 255;
    int row = r & 127;
    int ch = (c & 31) >> 3;
    int chp = ch ^ ((row >> 1) & 3);
    size_t off = ((size_t)(r >> 7) * 8 + (c >> 5)) * 4096 + row * 32 + chp * 8 + (c & 7);
    o[off] = __float2half(x[(size_t)r * 257 + c]);
}
__global__ __launch_bounds__(256) void conv_w(const float* __restrict__ w,
                                              __half* __restrict__ o, int n,
                                              int kbits, int C) {
    int i = blockIdx.x * 256 + threadIdx.x;
    if (i >= n) return;
    int r = i >> kbits, c = i & ((1 << kbits) - 1);
    int row = r & 127;
    int ch = (c & 31) >> 3;
    int chp = ch ^ ((row >> 1) & 3);
    size_t off = ((size_t)(r >> 7) * C + (c >> 5)) * 4096 + row * 32 + chp * 8 + (c & 7);
    o[off] = __float2half(w[i]);
}

// ---------------- bulk-TMA HMMA GEMM (mma.sync m16n8k16 fp16) ---------------
// C[M,N] = A[M,K] @ B[N,K]^T + bias.  CTA tile 128x128x32, 8 warps (2x4),
// warp tile 64x32, 256 threads, 2 CTAs/SM (reg-limited).
// 4-stage ring; thread 0 issues ONE cp.async.bulk per operand per stage
// (pre-swizzled contiguous image spans) + expect_tx.
// MODE 0: fp32 out (plain).  MODE 1: relu + fp16 out in image form (C=32).
constexpr int NST    = 4;
constexpr int ROWB   = 64;
constexpr int T_T    = 128 * ROWB;           // 8192 B per operand tile
constexpr int STAGE  = 2 * T_T;              // 16384 B
constexpr int SMEM_MAIN  = NST * STAGE;      // 65536 B
constexpr int SMEM_BYTES = SMEM_MAIN + 128;

template <int MODE>
__global__ __launch_bounds__(256, 2) void hmma_gemm(
    const __half* __restrict__ A, const __half* __restrict__ B,
    const float* __restrict__ bias, int K, int ldc,
    float* __restrict__ Cf, __half* __restrict__ Ch)
{
    extern __shared__ __align__(128) char smem[];
    const uint32_t sb = smem_u32(smem);
    const int tid = threadIdx.x;
    const int w = tid >> 5, lane = tid & 31;
    const int wm = w >> 2, wn = w & 3;        // 2x4 warp grid
    const int gid = lane >> 2, tig = lane & 3;
    const int m0 = blockIdx.y * 128, n0 = blockIdx.x * 128;
    const uint32_t mb_full  = sb + SMEM_MAIN;
    const uint32_t mb_empty = sb + SMEM_MAIN + 64;
    const int C = K >> 5;

    if (tid < NST) {
        MBAR_INIT(mb_full  + tid * 8, 1);     // expect_tx arrive from thread 0
        MBAR_INIT(mb_empty + tid * 8, 8);     // one arrive per warp
    }
    __syncthreads();

    float acc[4][4][4];
#pragma unroll
    for (int i = 0; i < 4; i++)
#pragma unroll
        for (int j = 0; j < 4; j++)
#pragma unroll
            for (int t = 0; t < 4; t++) acc[i][j][t] = 0.f;

    auto issue_stage = [&](int s, int c) {    // thread 0 only
        const uint32_t st = sb + s * STAGE;
        MBAR_EXPECT_TX(mb_full + s * 8, (uint32_t)STAGE);
        bulk_cp(st,       A + ((size_t)blockIdx.y * C + c) * 4096, T_T, mb_full + s * 8);
        bulk_cp(st + T_T, B + ((size_t)blockIdx.x * C + c) * 4096, T_T, mb_full + s * 8);
    };

    const uint32_t lsel = (lane & 15), hsel = (lane >> 4);
    const uint32_t xr = (lsel >> 1) & 3;

    auto compute_stage = [&](int s) {
        const uint32_t st = sb + s * STAGE;
#pragma unroll
        for (int ks = 0; ks < 2; ks++) {
            uint32_t chp = ((uint32_t)(ks * 2) + hsel) ^ xr;
            uint32_t a_off = st + (wm * 64 + lsel) * ROWB + chp * 16;
            uint32_t b_off = st + T_T + (wn * 32 + lsel) * ROWB + chp * 16;
            uint32_t bh[2][4];
#pragma unroll
            for (int p = 0; p < 2; p++) ldmx4(bh[p], b_off + p * 16 * ROWB);
#pragma unroll
            for (int i = 0; i < 4; i++) {
                uint32_t ah[4];
                ldmx4(ah, a_off + i * 16 * ROWB);
#pragma unroll
                for (int j = 0; j < 4; j++) {
                    const int p = j >> 1, r = j & 1;
                    mma16816(acc[i][j], ah, bh[p][r], bh[p][r + 2]);
                }
            }
        }
    };

    if (tid == 0) {
        for (int s = 0; s < NST - 1 && s < C; s++) issue_stage(s, s);
    }
    for (int c = 0; c < C; c++) {
        const int s = c & 3;
        mbar_wait(mb_full + s * 8, (c >> 2) & 1);
        compute_stage(s);
        if (lane == 0)
            asm volatile("mbarrier.arrive.release.cta.shared::cta.b64 _, [%0];"
                         :: "r"(mb_empty + s * 8) : "memory");
        if (tid == 0) {
            const int cn = c + NST - 1;
            if (cn < C) {
                const int sn = cn & 3, k = cn >> 2;
                if (k >= 1) mbar_wait(mb_empty + sn * 8, (k - 1) & 1);
                issue_stage(sn, cn);
            }
        }
    }

    // epilogue
    const int mr = m0 + wm * 64;
    const int nc = n0 + wn * 32;
#pragma unroll
    for (int i = 0; i < 4; i++) {
#pragma unroll
        for (int j = 0; j < 4; j++) {
            int n = nc + j * 8 + tig * 2;
            float2 bv = *(const float2*)(bias + n);
            int r_lo = mr + i * 16 + gid;
            int r_hi = r_lo + 8;
            float v00 = acc[i][j][0] + bv.x, v01 = acc[i][j][1] + bv.y;
            float v10 = acc[i][j][2] + bv.x, v11 = acc[i][j][3] + bv.y;
            if (MODE == 1) {
                v00 = fmaxf(v00, 0.f); v01 = fmaxf(v01, 0.f);
                v10 = fmaxf(v10, 0.f); v11 = fmaxf(v11, 0.f);
                // write 128-row image for GEMM2 A (K=1024 -> C=32)
                int ch = (n & 31) >> 3;
#pragma unroll
                for (int t2 = 0; t2 < 2; t2++) {
                    int r = t2 ? r_hi : r_lo;
                    int row = r & 127;
                    int chp = ch ^ ((row >> 1) & 3);
                    size_t off = ((size_t)(r >> 7) * 32 + (n >> 5)) * 4096
                               + row * 32 + chp * 8 + (n & 7);
                    *(__half2*)(Ch + off) = t2
                        ? __halves2half2(__float2half(v10), __float2half(v11))
                        : __halves2half2(__float2half(v00), __float2half(v01));
                }
            } else {
                *(float2*)(Cf + (size_t)r_lo * ldc + n) = make_float2(v00, v01);
                *(float2*)(Cf + (size_t)r_hi * ldc + n) = make_float2(v10, v11);
            }
        }
    }
}

// ---------------- convex fixed-point + gather: 2 rows/warp, f32x2 SIMD ------
__global__ __launch_bounds__(256) void convex_gather2(
    const float* __restrict__ p, const float* __restrict__ x, float* __restrict__ out) {
    const unsigned FULL = 0xffffffffu;
    int warp = (blockIdx.x * blockDim.x + threadIdx.x) >> 5;   // < BB/2
    int lane = threadIdx.x & 31;
    int rowA = warp * 2, rowB = warp * 2 + 1;

    const float* pa = p + (size_t)rowA * NF + lane * 8;
    const float* pb = p + (size_t)rowB * NF + lane * 8;
    uint64_t e[8];
    {
        float4 a0 = *(const float4*)(pa);
        float4 a1 = *(const float4*)(pa + 4);
        float4 b0 = *(const float4*)(pb);
        float4 b1 = *(const float4*)(pb + 4);
        e[0] = pack2(a0.x, b0.x); e[1] = pack2(a0.y, b0.y);
        e[2] = pack2(a0.z, b0.z); e[3] = pack2(a0.w, b0.w);
        e[4] = pack2(a1.x, b1.x); e[5] = pack2(a1.y, b1.y);
        e[6] = pack2(a1.z, b1.z); e[7] = pack2(a1.w, b1.w);
    }
    const uint64_t HALF2 = pack2(0.5f, 0.5f);

#pragma unroll 2
    for (int it = 0; it < 100; ++it) {
        uint64_t lin = __shfl_up_sync(FULL, e[7], 1);
        uint64_t rin = __shfl_down_sync(FULL, e[0], 1);
        uint64_t n0 = min2(e[0], mul2(add2(lin,  e[1]), HALF2));
        uint64_t n1 = min2(e[1], mul2(add2(e[0], e[2]), HALF2));
        uint64_t n2 = min2(e[2], mul2(add2(e[1], e[3]), HALF2));
        uint64_t n3 = min2(e[3], mul2(add2(e[2], e[4]), HALF2));
        uint64_t n4 = min2(e[4], mul2(add2(e[3], e[5]), HALF2));
        uint64_t n5 = min2(e[5], mul2(add2(e[4], e[6]), HALF2));
        uint64_t n6 = min2(e[6], mul2(add2(e[5], e[7]), HALF2));
        uint64_t n7 = min2(e[7], mul2(add2(e[6], rin ), HALF2));
        if (lane == 0)  n0 = e[0];
        if (lane == 31) n7 = e[7];
        e[0] = n0; e[1] = n1; e[2] = n2; e[3] = n3;
        e[4] = n4; e[5] = n5; e[6] = n6; e[7] = n7;
    }

    float qa = x[(size_t)rowA * 257 + 256];
    float qb = x[(size_t)rowB * 257 + 256];
    int idxA = min(max((int)rintf(qa * 255.0f), 0), 255);
    int idxB = min(max((int)rintf(qb * 255.0f), 0), 255);
    int slA = idxA >> 3, sbA = idxA & 7;
    int slB = idxB >> 3, sbB = idxB & 7;
    float valA = 0.f, valB = 0.f;
#pragma unroll
    for (int j = 0; j < 8; j++) {
        uint64_t ta = __shfl_sync(FULL, e[j], slA);
        uint64_t tb = __shfl_sync(FULL, e[j], slB);
        float tax, tay, tbx, tby;
        unpack2(ta, tax, tay);
        unpack2(tb, tbx, tby);
        if (j == sbA) valA = tax;
        if (j == sbB) valB = tby;
    }
    if (lane == 0) {
        out[rowA] = valA;
        out[rowB] = valB;
    }
}

// ---------------- launch ----------------
extern "C" void kernel_launch(void* const* d_in, const int* in_sizes, int n_in,
                              void* d_out, int out_size) {
    const float* x  = (const float*)d_in[0];
    const float* W1 = (const float*)d_in[1];
    const float* b1 = (const float*)d_in[2];
    const float* W2 = (const float*)d_in[3];
    const float* b2 = (const float*)d_in[4];
    float* out = (float*)d_out;

    void *pa, *pw1, *pw2, *ph, *pp;
    cudaGetSymbolAddress(&pa, g_a);
    cudaGetSymbolAddress(&pw1, g_w1);
    cudaGetSymbolAddress(&pw2, g_w2);
    cudaGetSymbolAddress(&ph, g_h);
    cudaGetSymbolAddress(&pp, g_p);

    __half* a  = (__half*)pa;
    __half* w1 = (__half*)pw1;
    __half* w2 = (__half*)pw2;
    __half* h  = (__half*)ph;
    float* prm = (float*)pp;

    cudaFuncSetAttribute(hmma_gemm<0>, cudaFuncAttributeMaxDynamicSharedMemorySize, SMEM_BYTES);
    cudaFuncSetAttribute(hmma_gemm<1>, cudaFuncAttributeMaxDynamicSharedMemorySize, SMEM_BYTES);

    conv_x<<<BB * NI / 256, 256>>>(x, a);
    conv_w<<<NH * NI / 256, 256>>>(W1, w1, NH * NI, 8, 8);     // K=256, C=8
    conv_w<<<NF * NH / 256, 256>>>(W2, w2, NF * NH, 10, 32);   // K=1024, C=32

    // GEMM1: h = relu(x @ W1^T + b1) -> fp16 image
    hmma_gemm<1><<<dim3(NH / 128, BB / 128), 256, SMEM_BYTES>>>(
        a, w1, b1, NI, NH, nullptr, h);
    // GEMM2: prm = h @ W2^T + b2 (fp32 plain)
    hmma_gemm<0><<<dim3(NF / 128, BB / 128), 256, SMEM_BYTES>>>(
        h, w2, b2, NH, NF, prm, nullptr);

    convex_gather2<<<BB / 16, 256>>>(prm, x, out);
}